// round 8
// baseline (speedup 1.0000x reference)
#include <cuda_runtime.h>
#include <cuda_bf16.h>
#include <stdint.h>
#include <math.h>

namespace {
typedef unsigned long long ull;

constexpr int H = 128, TB = 32, NT = 256, NC = 10, NK = 8;
constexpr float EPS = 1e-5f;
constexpr int USP = 132;                     // us row pitch (floats)

// ---- SMEM byte offsets (from 1024-aligned base) ----
constexpr int OFF_AHI  = 0;                        // bf16 A-hi 32x128: 2 halves x 4KB
constexpr int OFF_ALO  = 8192;
constexpr int OFF_US   = 16384;                    // float[32][USP]
constexpr int OFF_WC   = OFF_US + TB * USP * 4;    // float[128][12]
constexpr int OFF_BIAS = OFF_WC + 128 * 12 * 4;    // float[4][128]
constexpr int OFF_GAM  = OFF_BIAS + 4 * 128 * 4;   // float[3][128]
constexpr int OFF_BET  = OFF_GAM + 3 * 128 * 4;
constexpr int OFF_BC   = OFF_BET + 3 * 128 * 4;    // float[16]
constexpr int SMEM_BYTES = OFF_BC + 64 + 1024;

// Weights pre-converted to mma-fragment order:
// index = ((layer*16 + ntile8)*8 + kstep)*32 + lane, payload = {b0hi,b1hi,b0lo,b1lo}
constexpr int NFRAG = 4 * 16 * 8 * 32;
__device__ uint4 g_bfrag[NFRAG];

__host__ __device__ __forceinline__ int swz128(int b) { return b ^ ((b >> 3) & 0x70); }

__device__ __forceinline__ uint32_t smem_u32(const void* p) {
    uint32_t a;
    asm("{ .reg .u64 t; cvta.to.shared.u64 t, %1; cvt.u32.u64 %0, t; }" : "=r"(a) : "l"(p));
    return a;
}

// ---- f32x2 packed math ----
__device__ __forceinline__ ull fma2(ull a, ull b, ull c) {
    ull d; asm("fma.rn.f32x2 %0, %1, %2, %3;" : "=l"(d) : "l"(a), "l"(b), "l"(c)); return d;
}
__device__ __forceinline__ ull add2(ull a, ull b) {
    ull d; asm("add.rn.f32x2 %0, %1, %2;" : "=l"(d) : "l"(a), "l"(b)); return d;
}
__device__ __forceinline__ ull mul2(ull a, ull b) {
    ull d; asm("mul.rn.f32x2 %0, %1, %2;" : "=l"(d) : "l"(a), "l"(b)); return d;
}
__device__ __forceinline__ ull pack2(float lo, float hi) {
    ull d; asm("mov.b64 %0, {%1, %2};" : "=l"(d) : "f"(lo), "f"(hi)); return d;
}
__device__ __forceinline__ float plo(ull v) { return __uint_as_float((unsigned)v); }
__device__ __forceinline__ float phi(ull v) { return __uint_as_float((unsigned)(v >> 32)); }

__device__ __forceinline__ void ldsm4(uint32_t& r0, uint32_t& r1, uint32_t& r2,
                                      uint32_t& r3, uint32_t addr) {
    asm volatile("ldmatrix.sync.aligned.m8n8.x4.shared.b16 {%0,%1,%2,%3}, [%4];"
                 : "=r"(r0), "=r"(r1), "=r"(r2), "=r"(r3) : "r"(addr));
}
__device__ __forceinline__ void mma_bf16(float* c, const uint32_t* a,
                                         uint32_t b0, uint32_t b1) {
    asm volatile("mma.sync.aligned.m16n8k16.row.col.f32.bf16.bf16.f32 "
                 "{%0,%1,%2,%3}, {%4,%5,%6,%7}, {%8,%9}, {%0,%1,%2,%3};"
                 : "+f"(c[0]), "+f"(c[1]), "+f"(c[2]), "+f"(c[3])
                 : "r"(a[0]), "r"(a[1]), "r"(a[2]), "r"(a[3]), "r"(b0), "r"(b1));
}

__device__ __forceinline__ float fast_tanh(float x) {
    float a = fabsf(x);
    float e = __expf(-2.0f * a);
    float t = __fdividef(1.0f - e, 1.0f + e);
    return copysignf(t, x);
}
__device__ __forceinline__ void split_bf16(float v, __nv_bfloat16& hi, __nv_bfloat16& lo) {
    hi = __float2bfloat16(v);
    lo = __float2bfloat16(v - __bfloat162float(hi));
}
__device__ __forceinline__ uint32_t packbf2(__nv_bfloat16 a, __nv_bfloat16 b) {
    __nv_bfloat162 p; p.x = a; p.y = b;
    return *reinterpret_cast<uint32_t*>(&p);
}
__device__ __forceinline__ ull packbf4(float a, float b, float c, float d, bool hi_part) {
    __nv_bfloat16 h0, l0, h1, l1, h2, l2, h3, l3;
    split_bf16(a, h0, l0); split_bf16(b, h1, l1);
    split_bf16(c, h2, l2); split_bf16(d, h3, l3);
    uint32_t u0 = hi_part ? packbf2(h0, h1) : packbf2(l0, l1);
    uint32_t u1 = hi_part ? packbf2(h2, h3) : packbf2(l2, l3);
    return (ull)u0 | ((ull)u1 << 32);
}

// One-time: W[k][n] fp32 -> per-lane mma B fragments (hi+lo packed in one uint4).
__global__ void convert_weights(const float* __restrict__ W_in,
                                const float* __restrict__ W_att) {
    int gidx = blockIdx.x * blockDim.x + threadIdx.x;
    if (gidx >= NFRAG) return;
    int lane = gidx & 31;
    int s    = (gidx >> 5) & 7;
    int nt   = (gidx >> 8) & 15;
    int layer = gidx >> 12;
    const float* W = (layer == 0) ? W_in : (W_att + (size_t)(layer - 1) * H * H);
    int n  = 8 * nt + (lane >> 2);
    int k0 = 16 * s + 2 * (lane & 3);
    float v00 = W[(k0 + 0) * H + n], v01 = W[(k0 + 1) * H + n];
    float v10 = W[(k0 + 8) * H + n], v11 = W[(k0 + 9) * H + n];
    __nv_bfloat16 h00, l00, h01, l01, h10, l10, h11, l11;
    split_bf16(v00, h00, l00); split_bf16(v01, h01, l01);
    split_bf16(v10, h10, l10); split_bf16(v11, h11, l11);
    uint4 f;
    f.x = packbf2(h00, h01);
    f.y = packbf2(h10, h11);
    f.z = packbf2(l00, l01);
    f.w = packbf2(l10, l11);
    g_bfrag[gidx] = f;
}

// Write 4 consecutive cols (4-aligned c0) of row into swizzled A hi/lo tiles.
__device__ __forceinline__ void write_A4(char* sm, int row, int c0,
                                         float v0, float v1, float v2, float v3) {
    int byz = (c0 >> 6) * 4096 + swz128(row * 128 + (c0 & 63) * 2);
    *(ull*)(sm + OFF_AHI + byz) = packbf4(v0, v1, v2, v3, true);
    *(ull*)(sm + OFF_ALO + byz) = packbf4(v0, v1, v2, v3, false);
}

__global__ void __launch_bounds__(NT, 3)
fused_kernel(const float* __restrict__ x,
             const float* __restrict__ b_in,
             const float* __restrict__ b_att,
             const float* __restrict__ gamma_,
             const float* __restrict__ beta_,
             const float* __restrict__ W_c,
             const float* __restrict__ b_c,
             float* __restrict__ out)
{
    extern __shared__ char smraw[];
    char* sm = (char*)(((uintptr_t)smraw + 1023) & ~(uintptr_t)1023);
    const int t = threadIdx.x, l = t & 31, w = t >> 5;   // warp w: cols 16w..16w+15
    const int erow = t >> 3, q = t & 7;   // epilogue: row 0..31, col residue 0..7
    const long row0 = (long)blockIdx.x * TB;
    const uint32_t sbase = smem_u32(sm);

    const int a_r = l & 15;
    const int a_koff = (l >> 4) * 8;

    // ---- init: x -> A tiles (32 rows), params ----
#pragma unroll
    for (int it = 0; it < 4; ++it) {
        int fidx = t + NT * it;                  // 1024 float4s
        int r = fidx >> 5, c4 = fidx & 31;
        float4 xv = *(const float4*)&x[(row0 + r) * H + 4 * c4];
        int sz = (c4 >> 4) * 4096 + swz128(r * 128 + ((4 * c4) & 63) * 2);
        *(ull*)(sm + OFF_AHI + sz) = packbf4(xv.x, xv.y, xv.z, xv.w, true);
        *(ull*)(sm + OFF_ALO + sz) = packbf4(xv.x, xv.y, xv.z, xv.w, false);
    }
    if (t < H) {
        ((float*)(sm + OFF_BIAS))[t] = b_in[t];
#pragma unroll
        for (int i = 0; i < 3; ++i) {
            ((float*)(sm + OFF_BIAS))[(i + 1) * 128 + t] = b_att[i * H + t];
            ((float*)(sm + OFF_GAM))[i * 128 + t] = gamma_[i * H + t];
            ((float*)(sm + OFF_BET))[i * 128 + t] = beta_[i * H + t];
        }
    }
    for (int idx = t; idx < 128 * 12; idx += NT) {
        int col = idx / 12, c = idx % 12;
        ((float*)(sm + OFF_WC))[idx] = (c < NC) ? W_c[col * NC + c] : 0.0f;
    }
    if (t < NC) ((float*)(sm + OFF_BC))[t] = b_c[t];
    __syncthreads();

    // Chebyshev expansion of exp on [-1,1], degree 7 (max abs err ~2.3e-7)
    const float cf[NK] = {
        0.9999998013203222f, 0.9999999009433100f, 0.5000063116460630f,
        0.1666679855982844f, 0.0416350112309906f, 0.0083285961068067f,
        0.0014392748705062f, 0.0002046999336094f };

    ull hp[8];                    // this thread's h pairs: chunk m -> cols 4q+32m..+3
    float* us = (float*)(sm + OFF_US);

    for (int gi = 0; gi < 4; ++gi) {
        // ---- mainloop: C = A @ W, bf16-split; B streamed from L2 ----
        float C[2][2][4];
#pragma unroll
        for (int mt = 0; mt < 2; ++mt)
#pragma unroll
            for (int j = 0; j < 2; ++j)
#pragma unroll
                for (int e2 = 0; e2 < 4; ++e2) C[mt][j][e2] = 0.0f;

        const uint4* bf_base = g_bfrag + ((gi * 16 + 2 * w) * 8) * 32 + l;
#pragma unroll
        for (int s = 0; s < 8; ++s) {
            uint4 f0 = __ldg(bf_base + s * 32);
            uint4 f1 = __ldg(bf_base + (8 + s) * 32);
            const int khalf = s >> 2, kc0 = (s & 3) * 16;
#pragma unroll
            for (int mt = 0; mt < 2; ++mt) {
                int ra = 16 * mt + a_r;
                uint32_t off = khalf * 4096 + (uint32_t)swz128(ra * 128 + (kc0 + a_koff) * 2);
                uint32_t ah[4], al[4];
                ldsm4(ah[0], ah[1], ah[2], ah[3], sbase + OFF_AHI + off);
                ldsm4(al[0], al[1], al[2], al[3], sbase + OFF_ALO + off);
                mma_bf16(C[mt][0], ah, f0.x, f0.y);
                mma_bf16(C[mt][0], ah, f0.z, f0.w);
                mma_bf16(C[mt][0], al, f0.x, f0.y);
                mma_bf16(C[mt][1], ah, f1.x, f1.y);
                mma_bf16(C[mt][1], ah, f1.z, f1.w);
                mma_bf16(C[mt][1], al, f1.x, f1.y);
            }
        }

        // ---- fragment epilogue: +bias (tanh for gi>0) -> us ----
        const float* biasL = (const float*)(sm + OFF_BIAS) + gi * 128;
#pragma unroll
        for (int mt = 0; mt < 2; ++mt)
#pragma unroll
            for (int j = 0; j < 2; ++j) {
                int col0 = 16 * w + 8 * j + 2 * (l & 3);
                float2 b2 = *(const float2*)&biasL[col0];
                float v0 = C[mt][j][0] + b2.x, v1 = C[mt][j][1] + b2.y;
                float v2 = C[mt][j][2] + b2.x, v3 = C[mt][j][3] + b2.y;
                if (gi > 0) {
                    v0 = fast_tanh(v0); v1 = fast_tanh(v1);
                    v2 = fast_tanh(v2); v3 = fast_tanh(v3);
                }
                int r = 16 * mt + (l >> 2);
                *(float2*)&us[r * USP + col0]       = make_float2(v0, v1);
                *(float2*)&us[(r + 8) * USP + col0] = make_float2(v2, v3);
            }
        __syncthreads();

        const float* urow = us + erow * USP;
        if (gi == 0) {
#pragma unroll
            for (int m = 0; m < 4; ++m) {
                float4 v = *(const float4*)&urow[4 * q + 32 * m];
                hp[2 * m]     = pack2(v.x, v.y);
                hp[2 * m + 1] = pack2(v.z, v.w);
                write_A4(sm, erow, 4 * q + 32 * m, v.x, v.y, v.z, v.w);
            }
        } else {
            ull uP[8];
#pragma unroll
            for (int m = 0; m < 4; ++m) {
                float4 v = *(const float4*)&urow[4 * q + 32 * m];
                uP[2 * m]     = pack2(v.x, v.y);
                uP[2 * m + 1] = pack2(v.z, v.w);
            }
            // moments S_k = sum u^k h, T_k = sum u^k (packed pairs)
            const ull ONE2 = 0x3F8000003F800000ull;
            ull Sa[NK], Ta[NK];
#pragma unroll
            for (int k = 0; k < NK; ++k) { Sa[k] = 0ull; Ta[k] = 0ull; }
#pragma unroll
            for (int m = 0; m < 8; ++m) {
                ull pw = ONE2;
#pragma unroll
                for (int k = 0; k < NK; ++k) {
                    Sa[k] = fma2(pw, hp[m], Sa[k]);
                    Ta[k] = add2(Ta[k], pw);
                    pw = mul2(pw, uP[m]);
                }
            }
            ull S2[NK], T2[NK];
#pragma unroll
            for (int k = 0; k < NK; ++k) {
                float s = plo(Sa[k]) + phi(Sa[k]);
                float tt = plo(Ta[k]) + phi(Ta[k]);
                s += __shfl_xor_sync(0xffffffffu, s, 1);
                s += __shfl_xor_sync(0xffffffffu, s, 2);
                s += __shfl_xor_sync(0xffffffffu, s, 4);
                tt += __shfl_xor_sync(0xffffffffu, tt, 1);
                tt += __shfl_xor_sync(0xffffffffu, tt, 2);
                tt += __shfl_xor_sync(0xffffffffu, tt, 4);
                s *= cf[k];
                tt *= cf[k];
                S2[k] = pack2(s, s);
                T2[k] = pack2(tt, tt);
            }
            // Horner: y = h + N(u)/D(u); LN stats; overwrite hp with y
            float sum = 0.0f, sq = 0.0f;
#pragma unroll
            for (int m = 0; m < 8; ++m) {
                ull N = S2[NK - 1], D = T2[NK - 1];
#pragma unroll
                for (int k = NK - 2; k >= 0; --k) {
                    N = fma2(N, uP[m], S2[k]);
                    D = fma2(D, uP[m], T2[k]);
                }
                float y0 = plo(hp[m]) + __fdividef(plo(N), plo(D));
                float y1 = phi(hp[m]) + __fdividef(phi(N), phi(D));
                hp[m] = pack2(y0, y1);
                sum += y0 + y1;
                sq = fmaf(y0, y0, sq);
                sq = fmaf(y1, y1, sq);
            }
            sum += __shfl_xor_sync(0xffffffffu, sum, 1);
            sum += __shfl_xor_sync(0xffffffffu, sum, 2);
            sum += __shfl_xor_sync(0xffffffffu, sum, 4);
            sq  += __shfl_xor_sync(0xffffffffu, sq, 1);
            sq  += __shfl_xor_sync(0xffffffffu, sq, 2);
            sq  += __shfl_xor_sync(0xffffffffu, sq, 4);
            float mu = sum * (1.0f / H);
            float rs = rsqrtf(sq * (1.0f / H) - mu * mu + EPS);
            const float* gam = (const float*)(sm + OFF_GAM) + (gi - 1) * 128;
            const float* bet = (const float*)(sm + OFF_BET) + (gi - 1) * 128;
#pragma unroll
            for (int m = 0; m < 4; ++m) {
                int c0 = 4 * q + 32 * m;
                float h0 = (plo(hp[2*m])   - mu) * rs * gam[c0]     + bet[c0];
                float h1 = (phi(hp[2*m])   - mu) * rs * gam[c0 + 1] + bet[c0 + 1];
                float h2 = (plo(hp[2*m+1]) - mu) * rs * gam[c0 + 2] + bet[c0 + 2];
                float h3 = (phi(hp[2*m+1]) - mu) * rs * gam[c0 + 3] + bet[c0 + 3];
                hp[2*m]     = pack2(h0, h1);
                hp[2*m + 1] = pack2(h2, h3);
                if (gi < 3) write_A4(sm, erow, c0, h0, h1, h2, h3);
            }
        }
        __syncthreads();
    }

    // ---- classifier: logits = h @ W_c + b_c ----
    {
        const float* wc = (const float*)(sm + OFF_WC);
        float a[10];
#pragma unroll
        for (int c = 0; c < 10; ++c) a[c] = 0.0f;
#pragma unroll
        for (int m = 0; m < 8; ++m) {
#pragma unroll
            for (int pp = 0; pp < 2; ++pp) {
                int col = 4 * q + 32 * (m >> 1) + 2 * (m & 1) + pp;
                float hv = pp ? phi(hp[m]) : plo(hp[m]);
                const float4* wr = (const float4*)&wc[col * 12];
                float4 w0 = wr[0], w1 = wr[1], w2 = wr[2];
                a[0] = fmaf(hv, w0.x, a[0]);  a[1] = fmaf(hv, w0.y, a[1]);
                a[2] = fmaf(hv, w0.z, a[2]);  a[3] = fmaf(hv, w0.w, a[3]);
                a[4] = fmaf(hv, w1.x, a[4]);  a[5] = fmaf(hv, w1.y, a[5]);
                a[6] = fmaf(hv, w1.z, a[6]);  a[7] = fmaf(hv, w1.w, a[7]);
                a[8] = fmaf(hv, w2.x, a[8]);  a[9] = fmaf(hv, w2.y, a[9]);
            }
        }
#pragma unroll
        for (int c = 0; c < NC; ++c) {
            a[c] += __shfl_xor_sync(0xffffffffu, a[c], 1);
            a[c] += __shfl_xor_sync(0xffffffffu, a[c], 2);
            a[c] += __shfl_xor_sync(0xffffffffu, a[c], 4);
        }
        if (q == 0) {
            const float* bc = (const float*)(sm + OFF_BC);
#pragma unroll
            for (int c = 0; c < NC; ++c)
                out[(row0 + erow) * NC + c] = a[c] + bc[c];
        }
    }
}

}  // namespace

extern "C" void kernel_launch(void* const* d_in, const int* in_sizes, int n_in,
                              void* d_out, int out_size)
{
    const float* x     = (const float*)d_in[0];
    const float* W_in  = (const float*)d_in[1];
    const float* b_in  = (const float*)d_in[2];
    const float* W_att = (const float*)d_in[3];
    const float* b_att = (const float*)d_in[4];
    const float* gamma = (const float*)d_in[5];
    const float* beta  = (const float*)d_in[6];
    const float* W_c   = (const float*)d_in[7];
    const float* b_c   = (const float*)d_in[8];
    float* out = (float*)d_out;

    convert_weights<<<64, 256>>>(W_in, W_att);

    const int B = in_sizes[0] / H;
    const int grid = B / TB;                  // 16384/32 = 512 CTAs, 3 per SM

    cudaFuncSetAttribute(fused_kernel,
                         cudaFuncAttributeMaxDynamicSharedMemorySize, SMEM_BYTES);
    fused_kernel<<<grid, NT, SMEM_BYTES>>>(x, b_in, b_att, gamma, beta, W_c, b_c, out);
}

// round 9
// speedup vs baseline: 1.2110x; 1.2110x over previous
#include <cuda_runtime.h>
#include <cuda_bf16.h>
#include <stdint.h>
#include <math.h>

namespace {
typedef unsigned long long ull;

constexpr int H = 128, TB = 64, NT = 256, NC = 10, NK = 8;
constexpr float EPS = 1e-5f;
constexpr int USP = 132;                     // us row pitch (floats)

// ---- SMEM byte offsets (from 1024-aligned base) ----
constexpr int OFF_AHI  = 0;                        // bf16 A-hi tile 64x128 (8KB x2 halves)
constexpr int OFF_ALO  = 16384;                    // bf16 A-lo
constexpr int OFF_US   = 32768;                    // float[64][USP]
constexpr int OFF_WC   = OFF_US + TB * USP * 4;    // float[128][12]
constexpr int OFF_BIAS = OFF_WC + 128 * 12 * 4;    // float[4][128]
constexpr int OFF_GAM  = OFF_BIAS + 4 * 128 * 4;   // float[3][128]
constexpr int OFF_BET  = OFF_GAM + 3 * 128 * 4;
constexpr int OFF_BC   = OFF_BET + 3 * 128 * 4;    // float[16]
constexpr int SMEM_BYTES = OFF_BC + 64 + 1024;

// Weights pre-converted to mma-fragment order:
// index = ((layer*16 + ntile)*8 + kstep)*32 + lane, payload = {b0hi,b1hi,b0lo,b1lo}
constexpr int NFRAG = 4 * 16 * 8 * 32;
__device__ uint4 g_bfrag[NFRAG];

__host__ __device__ __forceinline__ int swz128(int b) { return b ^ ((b >> 3) & 0x70); }

__device__ __forceinline__ uint32_t smem_u32(const void* p) {
    uint32_t a;
    asm("{ .reg .u64 t; cvta.to.shared.u64 t, %1; cvt.u32.u64 %0, t; }" : "=r"(a) : "l"(p));
    return a;
}

// ---- f32x2 packed math ----
__device__ __forceinline__ ull fma2(ull a, ull b, ull c) {
    ull d; asm("fma.rn.f32x2 %0, %1, %2, %3;" : "=l"(d) : "l"(a), "l"(b), "l"(c)); return d;
}
__device__ __forceinline__ ull add2(ull a, ull b) {
    ull d; asm("add.rn.f32x2 %0, %1, %2;" : "=l"(d) : "l"(a), "l"(b)); return d;
}
__device__ __forceinline__ ull mul2(ull a, ull b) {
    ull d; asm("mul.rn.f32x2 %0, %1, %2;" : "=l"(d) : "l"(a), "l"(b)); return d;
}
__device__ __forceinline__ ull pack2(float lo, float hi) {
    ull d; asm("mov.b64 %0, {%1, %2};" : "=l"(d) : "f"(lo), "f"(hi)); return d;
}
__device__ __forceinline__ float plo(ull v) { return __uint_as_float((unsigned)v); }
__device__ __forceinline__ float phi(ull v) { return __uint_as_float((unsigned)(v >> 32)); }

__device__ __forceinline__ void ldsm4(uint32_t& r0, uint32_t& r1, uint32_t& r2,
                                      uint32_t& r3, uint32_t addr) {
    asm volatile("ldmatrix.sync.aligned.m8n8.x4.shared.b16 {%0,%1,%2,%3}, [%4];"
                 : "=r"(r0), "=r"(r1), "=r"(r2), "=r"(r3) : "r"(addr));
}
__device__ __forceinline__ void mma_bf16(float* c, const uint32_t* a,
                                         uint32_t b0, uint32_t b1) {
    asm volatile("mma.sync.aligned.m16n8k16.row.col.f32.bf16.bf16.f32 "
                 "{%0,%1,%2,%3}, {%4,%5,%6,%7}, {%8,%9}, {%0,%1,%2,%3};"
                 : "+f"(c[0]), "+f"(c[1]), "+f"(c[2]), "+f"(c[3])
                 : "r"(a[0]), "r"(a[1]), "r"(a[2]), "r"(a[3]), "r"(b0), "r"(b1));
}

__device__ __forceinline__ float fast_tanh(float x) {
    float a = fabsf(x);
    float e = __expf(-2.0f * a);
    float t = __fdividef(1.0f - e, 1.0f + e);
    return copysignf(t, x);
}
__device__ __forceinline__ void split_bf16(float v, __nv_bfloat16& hi, __nv_bfloat16& lo) {
    hi = __float2bfloat16(v);
    lo = __float2bfloat16(v - __bfloat162float(hi));
}
__device__ __forceinline__ uint32_t packbf2(__nv_bfloat16 a, __nv_bfloat16 b) {
    __nv_bfloat162 p; p.x = a; p.y = b;
    return *reinterpret_cast<uint32_t*>(&p);
}

// One-time: W[k][n] fp32 -> per-lane mma B fragments (hi+lo packed in one uint4).
// m16n8k16 B fragment: lane l, reg0 holds B[2*(l%4)+{0,1}][l/4], reg1 k+8.
__global__ void convert_weights(const float* __restrict__ W_in,
                                const float* __restrict__ W_att) {
    int gidx = blockIdx.x * blockDim.x + threadIdx.x;   // 16384
    if (gidx >= NFRAG) return;
    int lane = gidx & 31;
    int s    = (gidx >> 5) & 7;
    int nt   = (gidx >> 8) & 15;
    int layer = gidx >> 12;
    const float* W = (layer == 0) ? W_in : (W_att + (size_t)(layer - 1) * H * H);
    int n  = 8 * nt + (lane >> 2);
    int k0 = 16 * s + 2 * (lane & 3);
    float v00 = W[(k0 + 0) * H + n], v01 = W[(k0 + 1) * H + n];
    float v10 = W[(k0 + 8) * H + n], v11 = W[(k0 + 9) * H + n];
    __nv_bfloat16 h00, l00, h01, l01, h10, l10, h11, l11;
    split_bf16(v00, h00, l00); split_bf16(v01, h01, l01);
    split_bf16(v10, h10, l10); split_bf16(v11, h11, l11);
    uint4 f;
    f.x = packbf2(h00, h01);   // b0 hi
    f.y = packbf2(h10, h11);   // b1 hi
    f.z = packbf2(l00, l01);   // b0 lo
    f.w = packbf2(l10, l11);   // b1 lo
    g_bfrag[gidx] = f;
}

__device__ __forceinline__ void write_A1(char* sm, int row, int col, float v) {
    int byz = (col >> 6) * 8192 + swz128(row * 128 + (col & 63) * 2);
    __nv_bfloat16 hi, lo;
    split_bf16(v, hi, lo);
    *(__nv_bfloat16*)(sm + OFF_AHI + byz) = hi;
    *(__nv_bfloat16*)(sm + OFF_ALO + byz) = lo;
}

__global__ void __launch_bounds__(NT, 2)
fused_kernel(const float* __restrict__ x,
             const float* __restrict__ b_in,
             const float* __restrict__ b_att,
             const float* __restrict__ gamma_,
             const float* __restrict__ beta_,
             const float* __restrict__ W_c,
             const float* __restrict__ b_c,
             float* __restrict__ out)
{
    extern __shared__ char smraw[];
    char* sm = (char*)(((uintptr_t)smraw + 1023) & ~(uintptr_t)1023);
    const int t = threadIdx.x, l = t & 31, w = t >> 5;
    const int wm = w & 1, wn = w >> 1;           // warp tile: rows 32wm.., cols 32wn..
    const int erow = t >> 2, q = t & 3;          // epilogue: row (0..63), col residue
    const long row0 = (long)blockIdx.x * TB;
    const uint32_t sbase = smem_u32(sm);

    // ldmatrix per-lane address components
    const int a_r = l & 15;
    const int a_koff = (l >> 4) * 8;

    // ---- init: x -> A tiles (64 rows), params ----
#pragma unroll
    for (int it = 0; it < 8; ++it) {
        int fidx = t + NT * it;                  // 2048 float4s
        int r = fidx >> 5, c4 = fidx & 31;
        float4 xv = *(const float4*)&x[(row0 + r) * H + 4 * c4];
        int sz = (c4 >> 4) * 8192 + swz128(r * 128 + ((4 * c4) & 63) * 2);
        __nv_bfloat16 h0, h1, h2, h3, l0, l1, l2, l3;
        split_bf16(xv.x, h0, l0); split_bf16(xv.y, h1, l1);
        split_bf16(xv.z, h2, l2); split_bf16(xv.w, h3, l3);
        *(uint32_t*)(sm + OFF_AHI + sz)     = packbf2(h0, h1);
        *(uint32_t*)(sm + OFF_AHI + sz + 4) = packbf2(h2, h3);
        *(uint32_t*)(sm + OFF_ALO + sz)     = packbf2(l0, l1);
        *(uint32_t*)(sm + OFF_ALO + sz + 4) = packbf2(l2, l3);
    }
    if (t < H) {
        ((float*)(sm + OFF_BIAS))[t] = b_in[t];
#pragma unroll
        for (int i = 0; i < 3; ++i) {
            ((float*)(sm + OFF_BIAS))[(i + 1) * 128 + t] = b_att[i * H + t];
            ((float*)(sm + OFF_GAM))[i * 128 + t] = gamma_[i * H + t];
            ((float*)(sm + OFF_BET))[i * 128 + t] = beta_[i * H + t];
        }
    }
    for (int idx = t; idx < 128 * 12; idx += NT) {
        int col = idx / 12, c = idx % 12;
        ((float*)(sm + OFF_WC))[idx] = (c < NC) ? W_c[col * NC + c] : 0.0f;
    }
    if (t < NC) ((float*)(sm + OFF_BC))[t] = b_c[t];
    __syncthreads();

    // Degree-7 polynomial fit of exp on [-1,1] (Chebyshev; max abs err ~2.3e-7)
    const float cf[NK] = {
        0.9999998013203222f, 0.9999999009433100f, 0.5000063116460630f,
        0.1666679855982844f, 0.0416350112309906f, 0.0083285961068067f,
        0.0014392748705062f, 0.0002046999336094f };

    ull hp[16];                                  // this thread's h: cols q+8m, q+8m+4
    float* us = (float*)(sm + OFF_US);

    for (int gi = 0; gi < 4; ++gi) {
        // ---- mainloop: C = A @ W, bf16-split, B streamed from L2 in fragment order ----
        float C[2][4][4];
#pragma unroll
        for (int mt = 0; mt < 2; ++mt)
#pragma unroll
            for (int nt = 0; nt < 4; ++nt)
#pragma unroll
                for (int e2 = 0; e2 < 4; ++e2) C[mt][nt][e2] = 0.0f;

        const uint4* bf_base = g_bfrag + ((gi * 16 + 4 * wn) * 8) * 32 + l;
#pragma unroll
        for (int s = 0; s < 8; ++s) {
            uint4 f[4];
#pragma unroll
            for (int j = 0; j < 4; ++j)
                f[j] = __ldg(bf_base + (j * 8 + s) * 32);

            const int khalf = s >> 2, kc0 = (s & 3) * 16;
#pragma unroll
            for (int mt = 0; mt < 2; ++mt) {
                int ra = 32 * wm + 16 * mt + a_r;
                uint32_t off = khalf * 8192 + (uint32_t)swz128(ra * 128 + (kc0 + a_koff) * 2);
                uint32_t ah[4], al[4];
                ldsm4(ah[0], ah[1], ah[2], ah[3], sbase + OFF_AHI + off);
                ldsm4(al[0], al[1], al[2], al[3], sbase + OFF_ALO + off);
#pragma unroll
                for (int j = 0; j < 4; ++j) {
                    mma_bf16(C[mt][j], ah, f[j].x, f[j].y);   // Ahi*Bhi
                    mma_bf16(C[mt][j], ah, f[j].z, f[j].w);   // Ahi*Blo
                    mma_bf16(C[mt][j], al, f[j].x, f[j].y);   // Alo*Bhi
                }
            }
        }

        // ---- fragment epilogue: +bias (tanh for gi>0) -> us ----
        const float* biasL = (const float*)(sm + OFF_BIAS) + gi * 128;
#pragma unroll
        for (int mt = 0; mt < 2; ++mt)
#pragma unroll
            for (int nt = 0; nt < 4; ++nt) {
                int col0 = 32 * wn + 8 * nt + 2 * (l & 3);
                float2 b2 = *(const float2*)&biasL[col0];
                float v0 = C[mt][nt][0] + b2.x, v1 = C[mt][nt][1] + b2.y;
                float v2 = C[mt][nt][2] + b2.x, v3 = C[mt][nt][3] + b2.y;
                if (gi > 0) {
                    v0 = fast_tanh(v0); v1 = fast_tanh(v1);
                    v2 = fast_tanh(v2); v3 = fast_tanh(v3);
                }
                int r = 32 * wm + 16 * mt + (l >> 2);
                *(float2*)&us[r * USP + col0]       = make_float2(v0, v1);
                *(float2*)&us[(r + 8) * USP + col0] = make_float2(v2, v3);
            }
        __syncthreads();

        const float* urow = us + erow * USP + q;
        if (gi == 0) {
#pragma unroll
            for (int m = 0; m < 16; ++m) {
                float h0 = urow[8 * m], h1 = urow[8 * m + 4];
                hp[m] = pack2(h0, h1);
                write_A1(sm, erow, q + 8 * m, h0);
                write_A1(sm, erow, q + 8 * m + 4, h1);
            }
        } else {
            ull uP[16];
#pragma unroll
            for (int m = 0; m < 16; ++m) uP[m] = pack2(urow[8 * m], urow[8 * m + 4]);

            // moments S_k = sum u^k h, T_k = sum u^k (packed pairs); T_0 = 32/thread
            const ull ONE2 = 0x3F8000003F800000ull;
            ull Sa[NK], Ta[NK];
#pragma unroll
            for (int k = 0; k < NK; ++k) { Sa[k] = 0ull; Ta[k] = 0ull; }
#pragma unroll
            for (int m = 0; m < 16; ++m) {
                ull pw = uP[m];
                Sa[0] = fma2(ONE2, hp[m], Sa[0]);
#pragma unroll
                for (int k = 1; k < NK; ++k) {
                    Sa[k] = fma2(pw, hp[m], Sa[k]);
                    Ta[k] = add2(Ta[k], pw);
                    pw = mul2(pw, uP[m]);
                }
            }
            ull S2[NK], T2[NK];
#pragma unroll
            for (int k = 0; k < NK; ++k) {
                float s = plo(Sa[k]) + phi(Sa[k]);
                float tt = (k == 0) ? 32.0f : (plo(Ta[k]) + phi(Ta[k]));
                s += __shfl_xor_sync(0xffffffffu, s, 1);
                s += __shfl_xor_sync(0xffffffffu, s, 2);
                if (k == 0) {
                    tt = 128.0f;
                } else {
                    tt += __shfl_xor_sync(0xffffffffu, tt, 1);
                    tt += __shfl_xor_sync(0xffffffffu, tt, 2);
                }
                s *= cf[k];
                tt *= cf[k];
                S2[k] = pack2(s, s);
                T2[k] = pack2(tt, tt);
            }
            // Horner: y = h + N(u)/D(u); LN stats; overwrite hp with y
            float sum = 0.0f, sq = 0.0f;
#pragma unroll
            for (int m = 0; m < 16; ++m) {
                ull N = S2[NK - 1], D = T2[NK - 1];
#pragma unroll
                for (int k = NK - 2; k >= 0; --k) {
                    N = fma2(N, uP[m], S2[k]);
                    D = fma2(D, uP[m], T2[k]);
                }
                float y0 = plo(hp[m]) + __fdividef(plo(N), plo(D));
                float y1 = phi(hp[m]) + __fdividef(phi(N), phi(D));
                hp[m] = pack2(y0, y1);
                sum += y0 + y1;
                sq = fmaf(y0, y0, sq);
                sq = fmaf(y1, y1, sq);
            }
            sum += __shfl_xor_sync(0xffffffffu, sum, 1);
            sum += __shfl_xor_sync(0xffffffffu, sum, 2);
            sq  += __shfl_xor_sync(0xffffffffu, sq, 1);
            sq  += __shfl_xor_sync(0xffffffffu, sq, 2);
            float mu = sum * (1.0f / H);
            float rs = rsqrtf(sq * (1.0f / H) - mu * mu + EPS);
            const float* gam = (const float*)(sm + OFF_GAM) + (gi - 1) * 128;
            const float* bet = (const float*)(sm + OFF_BET) + (gi - 1) * 128;
#pragma unroll
            for (int m = 0; m < 16; ++m) {
                int c0 = q + 8 * m, c1 = c0 + 4;
                float h0 = (plo(hp[m]) - mu) * rs * gam[c0] + bet[c0];
                float h1 = (phi(hp[m]) - mu) * rs * gam[c1] + bet[c1];
                hp[m] = pack2(h0, h1);
                if (gi < 3) { write_A1(sm, erow, c0, h0); write_A1(sm, erow, c1, h1); }
            }
        }
        __syncthreads();
    }

    // ---- classifier: logits = h @ W_c + b_c ----
    {
        const float* wc = (const float*)(sm + OFF_WC);
        float a[10];
#pragma unroll
        for (int c = 0; c < 10; ++c) a[c] = 0.0f;
#pragma unroll
        for (int m = 0; m < 16; ++m) {
#pragma unroll
            for (int pp = 0; pp < 2; ++pp) {
                int col = q + 8 * m + 4 * pp;
                float hv = pp ? phi(hp[m]) : plo(hp[m]);
                const float4* wr = (const float4*)&wc[col * 12];
                float4 w0 = wr[0], w1 = wr[1], w2 = wr[2];
                a[0] = fmaf(hv, w0.x, a[0]);  a[1] = fmaf(hv, w0.y, a[1]);
                a[2] = fmaf(hv, w0.z, a[2]);  a[3] = fmaf(hv, w0.w, a[3]);
                a[4] = fmaf(hv, w1.x, a[4]);  a[5] = fmaf(hv, w1.y, a[5]);
                a[6] = fmaf(hv, w1.z, a[6]);  a[7] = fmaf(hv, w1.w, a[7]);
                a[8] = fmaf(hv, w2.x, a[8]);  a[9] = fmaf(hv, w2.y, a[9]);
            }
        }
#pragma unroll
        for (int c = 0; c < NC; ++c) {
            a[c] += __shfl_xor_sync(0xffffffffu, a[c], 1);
            a[c] += __shfl_xor_sync(0xffffffffu, a[c], 2);
        }
        if (q == 0) {
            const float* bc = (const float*)(sm + OFF_BC);
#pragma unroll
            for (int c = 0; c < NC; ++c)
                out[(row0 + erow) * NC + c] = a[c] + bc[c];
        }
    }
}

}  // namespace

extern "C" void kernel_launch(void* const* d_in, const int* in_sizes, int n_in,
                              void* d_out, int out_size)
{
    const float* x     = (const float*)d_in[0];
    const float* W_in  = (const float*)d_in[1];
    const float* b_in  = (const float*)d_in[2];
    const float* W_att = (const float*)d_in[3];
    const float* b_att = (const float*)d_in[4];
    const float* gamma = (const float*)d_in[5];
    const float* beta  = (const float*)d_in[6];
    const float* W_c   = (const float*)d_in[7];
    const float* b_c   = (const float*)d_in[8];
    float* out = (float*)d_out;

    convert_weights<<<64, 256>>>(W_in, W_att);

    const int B = in_sizes[0] / H;
    const int grid = B / TB;                  // 16384/64 = 256 CTAs, 2 per SM

    cudaFuncSetAttribute(fused_kernel,
                         cudaFuncAttributeMaxDynamicSharedMemorySize, SMEM_BYTES);
    fused_kernel<<<grid, NT, SMEM_BYTES>>>(x, b_in, b_att, gamma, beta, W_c, b_c, out);
}

// round 13
// speedup vs baseline: 1.2136x; 1.0021x over previous
#include <cuda_runtime.h>
#include <cuda_bf16.h>
#include <stdint.h>
#include <math.h>

namespace {
typedef unsigned long long ull;

constexpr int H = 128, TB = 64, NT = 256, NC = 10, NK = 8;
constexpr float EPS = 1e-5f;
constexpr int USP = 132;                     // us row pitch (floats)

// ---- SMEM byte offsets (from 1024-aligned base) ----
constexpr int OFF_AHI  = 0;                        // bf16 A-hi tile 64x128 (8KB x2 halves)
constexpr int OFF_ALO  = 16384;                    // bf16 A-lo
constexpr int OFF_US   = 32768;                    // float[64][USP]
constexpr int OFF_WC   = OFF_US + TB * USP * 4;    // float[128][12]
constexpr int OFF_BIAS = OFF_WC + 128 * 12 * 4;    // float[4][128]
constexpr int OFF_GAM  = OFF_BIAS + 4 * 128 * 4;   // float[3][128]
constexpr int OFF_BET  = OFF_GAM + 3 * 128 * 4;
constexpr int OFF_BC   = OFF_BET + 3 * 128 * 4;    // float[16]
constexpr int SMEM_BYTES = OFF_BC + 64 + 1024;

// Weights pre-converted to mma-fragment order:
// index = ((layer*16 + ntile)*8 + kstep)*32 + lane, payload = {b0hi,b1hi,b0lo,b1lo}
constexpr int NFRAG = 4 * 16 * 8 * 32;
__device__ uint4 g_bfrag[NFRAG];

__host__ __device__ __forceinline__ int swz128(int b) { return b ^ ((b >> 3) & 0x70); }

__device__ __forceinline__ uint32_t smem_u32(const void* p) {
    uint32_t a;
    asm("{ .reg .u64 t; cvta.to.shared.u64 t, %1; cvt.u32.u64 %0, t; }" : "=r"(a) : "l"(p));
    return a;
}

// ---- f32x2 packed math ----
__device__ __forceinline__ ull fma2(ull a, ull b, ull c) {
    ull d; asm("fma.rn.f32x2 %0, %1, %2, %3;" : "=l"(d) : "l"(a), "l"(b), "l"(c)); return d;
}
__device__ __forceinline__ ull add2(ull a, ull b) {
    ull d; asm("add.rn.f32x2 %0, %1, %2;" : "=l"(d) : "l"(a), "l"(b)); return d;
}
__device__ __forceinline__ ull mul2(ull a, ull b) {
    ull d; asm("mul.rn.f32x2 %0, %1, %2;" : "=l"(d) : "l"(a), "l"(b)); return d;
}
__device__ __forceinline__ ull pack2(float lo, float hi) {
    ull d; asm("mov.b64 %0, {%1, %2};" : "=l"(d) : "f"(lo), "f"(hi)); return d;
}
__device__ __forceinline__ float plo(ull v) { return __uint_as_float((unsigned)v); }
__device__ __forceinline__ float phi(ull v) { return __uint_as_float((unsigned)(v >> 32)); }

__device__ __forceinline__ void ldsm4(uint32_t& r0, uint32_t& r1, uint32_t& r2,
                                      uint32_t& r3, uint32_t addr) {
    asm volatile("ldmatrix.sync.aligned.m8n8.x4.shared.b16 {%0,%1,%2,%3}, [%4];"
                 : "=r"(r0), "=r"(r1), "=r"(r2), "=r"(r3) : "r"(addr));
}
__device__ __forceinline__ void mma_bf16(float* c, const uint32_t* a,
                                         uint32_t b0, uint32_t b1) {
    asm volatile("mma.sync.aligned.m16n8k16.row.col.f32.bf16.bf16.f32 "
                 "{%0,%1,%2,%3}, {%4,%5,%6,%7}, {%8,%9}, {%0,%1,%2,%3};"
                 : "+f"(c[0]), "+f"(c[1]), "+f"(c[2]), "+f"(c[3])
                 : "r"(a[0]), "r"(a[1]), "r"(a[2]), "r"(a[3]), "r"(b0), "r"(b1));
}

__device__ __forceinline__ float fast_tanh(float x) {
    float a = fabsf(x);
    float e = __expf(-2.0f * a);
    float t = __fdividef(1.0f - e, 1.0f + e);
    return copysignf(t, x);
}
__device__ __forceinline__ void split_bf16(float v, __nv_bfloat16& hi, __nv_bfloat16& lo) {
    hi = __float2bfloat16(v);
    lo = __float2bfloat16(v - __bfloat162float(hi));
}
__device__ __forceinline__ uint32_t packbf2(__nv_bfloat16 a, __nv_bfloat16 b) {
    __nv_bfloat162 p; p.x = a; p.y = b;
    return *reinterpret_cast<uint32_t*>(&p);
}
__device__ __forceinline__ ull packbf4(float a, float b, float c, float d, bool hi_part) {
    __nv_bfloat16 h0, l0, h1, l1, h2, l2, h3, l3;
    split_bf16(a, h0, l0); split_bf16(b, h1, l1);
    split_bf16(c, h2, l2); split_bf16(d, h3, l3);
    uint32_t u0 = hi_part ? packbf2(h0, h1) : packbf2(l0, l1);
    uint32_t u1 = hi_part ? packbf2(h2, h3) : packbf2(l2, l3);
    return (ull)u0 | ((ull)u1 << 32);
}

// One-time: W[k][n] fp32 -> per-lane mma B fragments (hi+lo packed in one uint4).
// m16n8k16 B fragment: lane l, reg0 holds B[2*(l%4)+{0,1}][l/4], reg1 k+8.
__global__ void convert_weights(const float* __restrict__ W_in,
                                const float* __restrict__ W_att) {
    int gidx = blockIdx.x * blockDim.x + threadIdx.x;   // 16384
    if (gidx >= NFRAG) return;
    int lane = gidx & 31;
    int s    = (gidx >> 5) & 7;
    int nt   = (gidx >> 8) & 15;
    int layer = gidx >> 12;
    const float* W = (layer == 0) ? W_in : (W_att + (size_t)(layer - 1) * H * H);
    int n  = 8 * nt + (lane >> 2);
    int k0 = 16 * s + 2 * (lane & 3);
    float v00 = W[(k0 + 0) * H + n], v01 = W[(k0 + 1) * H + n];
    float v10 = W[(k0 + 8) * H + n], v11 = W[(k0 + 9) * H + n];
    __nv_bfloat16 h00, l00, h01, l01, h10, l10, h11, l11;
    split_bf16(v00, h00, l00); split_bf16(v01, h01, l01);
    split_bf16(v10, h10, l10); split_bf16(v11, h11, l11);
    uint4 f;
    f.x = packbf2(h00, h01);   // b0 hi
    f.y = packbf2(h10, h11);   // b1 hi
    f.z = packbf2(l00, l01);   // b0 lo
    f.w = packbf2(l10, l11);   // b1 lo
    g_bfrag[gidx] = f;
}

// Write 4 consecutive cols (4-aligned c0) of row into swizzled A hi/lo tiles.
__device__ __forceinline__ void write_A4(char* sm, int row, int c0,
                                         float v0, float v1, float v2, float v3) {
    int byz = (c0 >> 6) * 8192 + swz128(row * 128 + (c0 & 63) * 2);
    *(ull*)(sm + OFF_AHI + byz) = packbf4(v0, v1, v2, v3, true);
    *(ull*)(sm + OFF_ALO + byz) = packbf4(v0, v1, v2, v3, false);
}

__global__ void __launch_bounds__(NT, 2)
fused_kernel(const float* __restrict__ x,
             const float* __restrict__ b_in,
             const float* __restrict__ b_att,
             const float* __restrict__ gamma_,
             const float* __restrict__ beta_,
             const float* __restrict__ W_c,
             const float* __restrict__ b_c,
             float* __restrict__ out)
{
    extern __shared__ char smraw[];
    char* sm = (char*)(((uintptr_t)smraw + 1023) & ~(uintptr_t)1023);
    const int t = threadIdx.x, l = t & 31, w = t >> 5;
    const int wm = w & 1, wn = w >> 1;           // warp tile: rows 32wm.., cols 32wn..
    const int erow = t >> 2, q = t & 3;          // epilogue: row (0..63), chunk residue
    const long row0 = (long)blockIdx.x * TB;
    const uint32_t sbase = smem_u32(sm);

    // ldmatrix per-lane address components
    const int a_r = l & 15;
    const int a_koff = (l >> 4) * 8;

    // ---- init: x -> A tiles (64 rows), params ----
#pragma unroll
    for (int it = 0; it < 8; ++it) {
        int fidx = t + NT * it;                  // 2048 float4s
        int r = fidx >> 5, c4 = fidx & 31;
        float4 xv = *(const float4*)&x[(row0 + r) * H + 4 * c4];
        int sz = (c4 >> 4) * 8192 + swz128(r * 128 + ((4 * c4) & 63) * 2);
        *(ull*)(sm + OFF_AHI + sz) = packbf4(xv.x, xv.y, xv.z, xv.w, true);
        *(ull*)(sm + OFF_ALO + sz) = packbf4(xv.x, xv.y, xv.z, xv.w, false);
    }
    if (t < H) {
        ((float*)(sm + OFF_BIAS))[t] = b_in[t];
#pragma unroll
        for (int i = 0; i < 3; ++i) {
            ((float*)(sm + OFF_BIAS))[(i + 1) * 128 + t] = b_att[i * H + t];
            ((float*)(sm + OFF_GAM))[i * 128 + t] = gamma_[i * H + t];
            ((float*)(sm + OFF_BET))[i * 128 + t] = beta_[i * H + t];
        }
    }
    for (int idx = t; idx < 128 * 12; idx += NT) {
        int col = idx / 12, c = idx % 12;
        ((float*)(sm + OFF_WC))[idx] = (c < NC) ? W_c[col * NC + c] : 0.0f;
    }
    if (t < NC) ((float*)(sm + OFF_BC))[t] = b_c[t];
    __syncthreads();

    // Degree-7 polynomial fit of exp on [-1,1] (Chebyshev; max abs err ~2.3e-7)
    const float cf[NK] = {
        0.9999998013203222f, 0.9999999009433100f, 0.5000063116460630f,
        0.1666679855982844f, 0.0416350112309906f, 0.0083285961068067f,
        0.0014392748705062f, 0.0002046999336094f };

    ull hp[16];          // this thread's h: chunk m -> cols 16m+4q+{0,1} and {2,3}
    float* us = (float*)(sm + OFF_US);

    for (int gi = 0; gi < 4; ++gi) {
        // ---- mainloop: C = A @ W, bf16-split, B streamed from L2 in fragment order ----
        float C[2][4][4];
#pragma unroll
        for (int mt = 0; mt < 2; ++mt)
#pragma unroll
            for (int nt = 0; nt < 4; ++nt)
#pragma unroll
                for (int e2 = 0; e2 < 4; ++e2) C[mt][nt][e2] = 0.0f;

        const uint4* bf_base = g_bfrag + ((gi * 16 + 4 * wn) * 8) * 32 + l;
#pragma unroll
        for (int s = 0; s < 8; ++s) {
            uint4 f[4];
#pragma unroll
            for (int j = 0; j < 4; ++j)
                f[j] = __ldg(bf_base + (j * 8 + s) * 32);

            const int khalf = s >> 2, kc0 = (s & 3) * 16;
#pragma unroll
            for (int mt = 0; mt < 2; ++mt) {
                int ra = 32 * wm + 16 * mt + a_r;
                uint32_t off = khalf * 8192 + (uint32_t)swz128(ra * 128 + (kc0 + a_koff) * 2);
                uint32_t ah[4], al[4];
                ldsm4(ah[0], ah[1], ah[2], ah[3], sbase + OFF_AHI + off);
                ldsm4(al[0], al[1], al[2], al[3], sbase + OFF_ALO + off);
#pragma unroll
                for (int j = 0; j < 4; ++j) {
                    mma_bf16(C[mt][j], ah, f[j].x, f[j].y);   // Ahi*Bhi
                    mma_bf16(C[mt][j], ah, f[j].z, f[j].w);   // Ahi*Blo
                    mma_bf16(C[mt][j], al, f[j].x, f[j].y);   // Alo*Bhi
                }
            }
        }

        // ---- fragment epilogue: +bias (tanh for gi>0) -> us ----
        const float* biasL = (const float*)(sm + OFF_BIAS) + gi * 128;
#pragma unroll
        for (int mt = 0; mt < 2; ++mt)
#pragma unroll
            for (int nt = 0; nt < 4; ++nt) {
                int col0 = 32 * wn + 8 * nt + 2 * (l & 3);
                float2 b2 = *(const float2*)&biasL[col0];
                float v0 = C[mt][nt][0] + b2.x, v1 = C[mt][nt][1] + b2.y;
                float v2 = C[mt][nt][2] + b2.x, v3 = C[mt][nt][3] + b2.y;
                if (gi > 0) {
                    v0 = fast_tanh(v0); v1 = fast_tanh(v1);
                    v2 = fast_tanh(v2); v3 = fast_tanh(v3);
                }
                int r = 32 * wm + 16 * mt + (l >> 2);
                *(float2*)&us[r * USP + col0]       = make_float2(v0, v1);
                *(float2*)&us[(r + 8) * USP + col0] = make_float2(v2, v3);
            }
        __syncthreads();

        const float* urow = us + erow * USP;
        if (gi == 0) {
#pragma unroll
            for (int m = 0; m < 8; ++m) {
                float4 v = *(const float4*)&urow[16 * m + 4 * q];
                hp[2 * m]     = pack2(v.x, v.y);
                hp[2 * m + 1] = pack2(v.z, v.w);
                write_A4(sm, erow, 16 * m + 4 * q, v.x, v.y, v.z, v.w);
            }
        } else {
            ull uP[16];
#pragma unroll
            for (int m = 0; m < 8; ++m) {
                float4 v = *(const float4*)&urow[16 * m + 4 * q];
                uP[2 * m]     = pack2(v.x, v.y);
                uP[2 * m + 1] = pack2(v.z, v.w);
            }

            // moments S_k = sum u^k h, T_k = sum u^k (packed pairs); T_0 known
            const ull ONE2 = 0x3F8000003F800000ull;
            ull Sa[NK], Ta[NK];
#pragma unroll
            for (int k = 0; k < NK; ++k) { Sa[k] = 0ull; Ta[k] = 0ull; }
#pragma unroll
            for (int m = 0; m < 16; ++m) {
                ull pw = uP[m];
                Sa[0] = fma2(ONE2, hp[m], Sa[0]);
#pragma unroll
                for (int k = 1; k < NK; ++k) {
                    Sa[k] = fma2(pw, hp[m], Sa[k]);
                    Ta[k] = add2(Ta[k], pw);
                    pw = mul2(pw, uP[m]);
                }
            }
            ull S2[NK], T2[NK];
#pragma unroll
            for (int k = 0; k < NK; ++k) {
                float s = plo(Sa[k]) + phi(Sa[k]);
                float tt = (k == 0) ? 32.0f : (plo(Ta[k]) + phi(Ta[k]));
                s += __shfl_xor_sync(0xffffffffu, s, 1);
                s += __shfl_xor_sync(0xffffffffu, s, 2);
                if (k == 0) {
                    tt = 128.0f;
                } else {
                    tt += __shfl_xor_sync(0xffffffffu, tt, 1);
                    tt += __shfl_xor_sync(0xffffffffu, tt, 2);
                }
                s *= cf[k];
                tt *= cf[k];
                S2[k] = pack2(s, s);
                T2[k] = pack2(tt, tt);
            }
            // Horner: y = h + N(u)/D(u); LN stats; overwrite hp with y
            float sum = 0.0f, sq = 0.0f;
#pragma unroll
            for (int m = 0; m < 16; ++m) {
                ull N = S2[NK - 1], D = T2[NK - 1];
#pragma unroll
                for (int k = NK - 2; k >= 0; --k) {
                    N = fma2(N, uP[m], S2[k]);
                    D = fma2(D, uP[m], T2[k]);
                }
                float y0 = plo(hp[m]) + __fdividef(plo(N), plo(D));
                float y1 = phi(hp[m]) + __fdividef(phi(N), phi(D));
                hp[m] = pack2(y0, y1);
                sum += y0 + y1;
                sq = fmaf(y0, y0, sq);
                sq = fmaf(y1, y1, sq);
            }
            sum += __shfl_xor_sync(0xffffffffu, sum, 1);
            sum += __shfl_xor_sync(0xffffffffu, sum, 2);
            sq  += __shfl_xor_sync(0xffffffffu, sq, 1);
            sq  += __shfl_xor_sync(0xffffffffu, sq, 2);
            float mu = sum * (1.0f / H);
            float rs = rsqrtf(sq * (1.0f / H) - mu * mu + EPS);
            const float* gam = (const float*)(sm + OFF_GAM) + (gi - 1) * 128;
            const float* bet = (const float*)(sm + OFF_BET) + (gi - 1) * 128;
#pragma unroll
            for (int m = 0; m < 8; ++m) {
                int c0 = 16 * m + 4 * q;
                float4 g4 = *(const float4*)&gam[c0];
                float4 be4 = *(const float4*)&bet[c0];
                float h0 = (plo(hp[2*m])   - mu) * rs * g4.x + be4.x;
                float h1 = (phi(hp[2*m])   - mu) * rs * g4.y + be4.y;
                float h2 = (plo(hp[2*m+1]) - mu) * rs * g4.z + be4.z;
                float h3 = (phi(hp[2*m+1]) - mu) * rs * g4.w + be4.w;
                hp[2*m]     = pack2(h0, h1);
                hp[2*m + 1] = pack2(h2, h3);
                if (gi < 3) write_A4(sm, erow, c0, h0, h1, h2, h3);
            }
        }
        __syncthreads();
    }

    // ---- classifier: logits = h @ W_c + b_c ----
    {
        const float* wc = (const float*)(sm + OFF_WC);
        float a[10];
#pragma unroll
        for (int c = 0; c < 10; ++c) a[c] = 0.0f;
#pragma unroll
        for (int m = 0; m < 16; ++m) {
#pragma unroll
            for (int pp = 0; pp < 2; ++pp) {
                int col = 16 * (m >> 1) + 4 * q + 2 * (m & 1) + pp;
                float hv = pp ? phi(hp[m]) : plo(hp[m]);
                const float4* wr = (const float4*)&wc[col * 12];
                float4 w0 = wr[0], w1 = wr[1], w2 = wr[2];
                a[0] = fmaf(hv, w0.x, a[0]);  a[1] = fmaf(hv, w0.y, a[1]);
                a[2] = fmaf(hv, w0.z, a[2]);  a[3] = fmaf(hv, w0.w, a[3]);
                a[4] = fmaf(hv, w1.x, a[4]);  a[5] = fmaf(hv, w1.y, a[5]);
                a[6] = fmaf(hv, w1.z, a[6]);  a[7] = fmaf(hv, w1.w, a[7]);
                a[8] = fmaf(hv, w2.x, a[8]);  a[9] = fmaf(hv, w2.y, a[9]);
            }
        }
#pragma unroll
        for (int c = 0; c < NC; ++c) {
            a[c] += __shfl_xor_sync(0xffffffffu, a[c], 1);
            a[c] += __shfl_xor_sync(0xffffffffu, a[c], 2);
        }
        if (q == 0) {
            const float* bc = (const float*)(sm + OFF_BC);
#pragma unroll
            for (int c = 0; c < NC; ++c)
                out[(row0 + erow) * NC + c] = a[c] + bc[c];
        }
    }
}

}  // namespace

extern "C" void kernel_launch(void* const* d_in, const int* in_sizes, int n_in,
                              void* d_out, int out_size)
{
    const float* x     = (const float*)d_in[0];
    const float* W_in  = (const float*)d_in[1];
    const float* b_in  = (const float*)d_in[2];
    const float* W_att = (const float*)d_in[3];
    const float* b_att = (const float*)d_in[4];
    const float* gamma = (const float*)d_in[5];
    const float* beta  = (const float*)d_in[6];
    const float* W_c   = (const float*)d_in[7];
    const float* b_c   = (const float*)d_in[8];
    float* out = (float*)d_out;

    convert_weights<<<64, 256>>>(W_in, W_att);

    const int B = in_sizes[0] / H;
    const int grid = B / TB;                  // 16384/64 = 256 CTAs, 2 per SM

    cudaFuncSetAttribute(fused_kernel,
                         cudaFuncAttributeMaxDynamicSharedMemorySize, SMEM_BYTES);
    fused_kernel<<<grid, NT, SMEM_BYTES>>>(x, b_in, b_att, gamma, beta, W_c, b_c, out);
}

// round 14
// speedup vs baseline: 1.3300x; 1.0959x over previous
#include <cuda_runtime.h>
#include <cuda_fp16.h>
#include <stdint.h>
#include <math.h>

namespace {
typedef unsigned long long ull;

constexpr int H = 128, TB = 64, NT = 256, NC = 10, NK = 8;
constexpr float EPS = 1e-5f;
constexpr int USP = 132;                     // us row pitch (floats)

// ---- SMEM byte offsets (from 1024-aligned base) ----
constexpr int OFF_A    = 0;                        // fp16 A tile 64x128: 2 k-halves x 8KB
constexpr int OFF_US   = 16384;                    // float[64][USP]
constexpr int OFF_WC   = OFF_US + TB * USP * 4;    // float[128][12]
constexpr int OFF_BIAS = OFF_WC + 128 * 12 * 4;    // float[4][128]
constexpr int OFF_GAM  = OFF_BIAS + 4 * 128 * 4;   // float[3][128]
constexpr int OFF_BET  = OFF_GAM + 3 * 128 * 4;
constexpr int OFF_BC   = OFF_BET + 3 * 128 * 4;    // float[16]
constexpr int SMEM_BYTES = OFF_BC + 64 + 1024;

// Weights pre-converted to mma-fragment order (fp16 hi/lo split):
// index = ((layer*16 + ntile)*8 + kstep)*32 + lane, payload = {b0hi,b1hi,b0lo,b1lo}
constexpr int NFRAG = 4 * 16 * 8 * 32;
__device__ uint4 g_bfrag[NFRAG];

__host__ __device__ __forceinline__ int swz128(int b) { return b ^ ((b >> 3) & 0x70); }

__device__ __forceinline__ uint32_t smem_u32(const void* p) {
    uint32_t a;
    asm("{ .reg .u64 t; cvta.to.shared.u64 t, %1; cvt.u32.u64 %0, t; }" : "=r"(a) : "l"(p));
    return a;
}

// ---- f32x2 packed math ----
__device__ __forceinline__ ull fma2(ull a, ull b, ull c) {
    ull d; asm("fma.rn.f32x2 %0, %1, %2, %3;" : "=l"(d) : "l"(a), "l"(b), "l"(c)); return d;
}
__device__ __forceinline__ ull add2(ull a, ull b) {
    ull d; asm("add.rn.f32x2 %0, %1, %2;" : "=l"(d) : "l"(a), "l"(b)); return d;
}
__device__ __forceinline__ ull mul2(ull a, ull b) {
    ull d; asm("mul.rn.f32x2 %0, %1, %2;" : "=l"(d) : "l"(a), "l"(b)); return d;
}
__device__ __forceinline__ ull pack2(float lo, float hi) {
    ull d; asm("mov.b64 %0, {%1, %2};" : "=l"(d) : "f"(lo), "f"(hi)); return d;
}
__device__ __forceinline__ float plo(ull v) { return __uint_as_float((unsigned)v); }
__device__ __forceinline__ float phi(ull v) { return __uint_as_float((unsigned)(v >> 32)); }

__device__ __forceinline__ void ldsm4(uint32_t& r0, uint32_t& r1, uint32_t& r2,
                                      uint32_t& r3, uint32_t addr) {
    asm volatile("ldmatrix.sync.aligned.m8n8.x4.shared.b16 {%0,%1,%2,%3}, [%4];"
                 : "=r"(r0), "=r"(r1), "=r"(r2), "=r"(r3) : "r"(addr));
}
__device__ __forceinline__ void mma_f16(float* c, const uint32_t* a,
                                        uint32_t b0, uint32_t b1) {
    asm volatile("mma.sync.aligned.m16n8k16.row.col.f32.f16.f16.f32 "
                 "{%0,%1,%2,%3}, {%4,%5,%6,%7}, {%8,%9}, {%0,%1,%2,%3};"
                 : "+f"(c[0]), "+f"(c[1]), "+f"(c[2]), "+f"(c[3])
                 : "r"(a[0]), "r"(a[1]), "r"(a[2]), "r"(a[3]), "r"(b0), "r"(b1));
}

__device__ __forceinline__ float fast_tanh(float x) {
    float a = fabsf(x);
    float e = __expf(-2.0f * a);
    float t = __fdividef(1.0f - e, 1.0f + e);
    return copysignf(t, x);
}
__device__ __forceinline__ uint32_t packh2(__half a, __half b) {
    __half2 p; p.x = a; p.y = b;
    return *reinterpret_cast<uint32_t*>(&p);
}
__device__ __forceinline__ ull packf16x4(float a, float b, float c, float d) {
    __half2 p0 = __floats2half2_rn(a, b);
    __half2 p1 = __floats2half2_rn(c, d);
    return (ull)(*reinterpret_cast<uint32_t*>(&p0)) |
           ((ull)(*reinterpret_cast<uint32_t*>(&p1)) << 32);
}

// One-time: W[k][n] fp32 -> per-lane mma B fragments, fp16 hi/lo split.
// m16n8k16 B fragment: lane l, reg0 holds B[2*(l%4)+{0,1}][l/4], reg1 k+8.
__global__ void convert_weights(const float* __restrict__ W_in,
                                const float* __restrict__ W_att) {
    int gidx = blockIdx.x * blockDim.x + threadIdx.x;   // 16384
    if (gidx >= NFRAG) return;
    int lane = gidx & 31;
    int s    = (gidx >> 5) & 7;
    int nt   = (gidx >> 8) & 15;
    int layer = gidx >> 12;
    const float* W = (layer == 0) ? W_in : (W_att + (size_t)(layer - 1) * H * H);
    int n  = 8 * nt + (lane >> 2);
    int k0 = 16 * s + 2 * (lane & 3);
    float v00 = W[(k0 + 0) * H + n], v01 = W[(k0 + 1) * H + n];
    float v10 = W[(k0 + 8) * H + n], v11 = W[(k0 + 9) * H + n];
    __half h00 = __float2half_rn(v00), h01 = __float2half_rn(v01);
    __half h10 = __float2half_rn(v10), h11 = __float2half_rn(v11);
    __half l00 = __float2half_rn(v00 - __half2float(h00));
    __half l01 = __float2half_rn(v01 - __half2float(h01));
    __half l10 = __float2half_rn(v10 - __half2float(h10));
    __half l11 = __float2half_rn(v11 - __half2float(h11));
    uint4 f;
    f.x = packh2(h00, h01);   // b0 hi
    f.y = packh2(h10, h11);   // b1 hi
    f.z = packh2(l00, l01);   // b0 lo
    f.w = packh2(l10, l11);   // b1 lo
    g_bfrag[gidx] = f;
}

// Write 4 consecutive cols (4-aligned c0) of row into the swizzled fp16 A tile.
__device__ __forceinline__ void write_A4(char* sm, int row, int c0,
                                         float v0, float v1, float v2, float v3) {
    int byz = (c0 >> 6) * 8192 + swz128(row * 128 + (c0 & 63) * 2);
    *(ull*)(sm + OFF_A + byz) = packf16x4(v0, v1, v2, v3);
}

__global__ void __launch_bounds__(NT, 2)
fused_kernel(const float* __restrict__ x,
             const float* __restrict__ b_in,
             const float* __restrict__ b_att,
             const float* __restrict__ gamma_,
             const float* __restrict__ beta_,
             const float* __restrict__ W_c,
             const float* __restrict__ b_c,
             float* __restrict__ out)
{
    extern __shared__ char smraw[];
    char* sm = (char*)(((uintptr_t)smraw + 1023) & ~(uintptr_t)1023);
    const int t = threadIdx.x, l = t & 31, w = t >> 5;
    const int wm = w & 1, wn = w >> 1;           // warp tile: rows 32wm.., cols 32wn..
    const int erow = t >> 2, q = t & 3;          // epilogue: row (0..63), chunk residue
    const long row0 = (long)blockIdx.x * TB;
    const uint32_t sbase = smem_u32(sm);

    // ldmatrix per-lane address components
    const int a_r = l & 15;
    const int a_koff = (l >> 4) * 8;

    // ---- init: x -> A tile (64 rows, fp16), params ----
#pragma unroll
    for (int it = 0; it < 8; ++it) {
        int fidx = t + NT * it;                  // 2048 float4s
        int r = fidx >> 5, c4 = fidx & 31;
        float4 xv = *(const float4*)&x[(row0 + r) * H + 4 * c4];
        int sz = (c4 >> 4) * 8192 + swz128(r * 128 + ((4 * c4) & 63) * 2);
        *(ull*)(sm + OFF_A + sz) = packf16x4(xv.x, xv.y, xv.z, xv.w);
    }
    if (t < H) {
        ((float*)(sm + OFF_BIAS))[t] = b_in[t];
#pragma unroll
        for (int i = 0; i < 3; ++i) {
            ((float*)(sm + OFF_BIAS))[(i + 1) * 128 + t] = b_att[i * H + t];
            ((float*)(sm + OFF_GAM))[i * 128 + t] = gamma_[i * H + t];
            ((float*)(sm + OFF_BET))[i * 128 + t] = beta_[i * H + t];
        }
    }
    for (int idx = t; idx < 128 * 12; idx += NT) {
        int col = idx / 12, c = idx % 12;
        ((float*)(sm + OFF_WC))[idx] = (c < NC) ? W_c[col * NC + c] : 0.0f;
    }
    if (t < NC) ((float*)(sm + OFF_BC))[t] = b_c[t];
    __syncthreads();

    // Degree-7 polynomial fit of exp on [-1,1] (Chebyshev; max abs err ~2.3e-7)
    const float cf[NK] = {
        0.9999998013203222f, 0.9999999009433100f, 0.5000063116460630f,
        0.1666679855982844f, 0.0416350112309906f, 0.0083285961068067f,
        0.0014392748705062f, 0.0002046999336094f };

    ull hp[16];          // this thread's h: chunk m -> cols 16m+4q+{0,1} and {2,3}
    float* us = (float*)(sm + OFF_US);

    for (int gi = 0; gi < 4; ++gi) {
        // ---- mainloop: C = A @ W, fp16 A x fp16-split B, streamed from L2 ----
        float C[2][4][4];
#pragma unroll
        for (int mt = 0; mt < 2; ++mt)
#pragma unroll
            for (int nt = 0; nt < 4; ++nt)
#pragma unroll
                for (int e2 = 0; e2 < 4; ++e2) C[mt][nt][e2] = 0.0f;

        const uint4* bf_base = g_bfrag + ((gi * 16 + 4 * wn) * 8) * 32 + l;
#pragma unroll
        for (int s = 0; s < 8; ++s) {
            uint4 f[4];
#pragma unroll
            for (int j = 0; j < 4; ++j)
                f[j] = __ldg(bf_base + (j * 8 + s) * 32);

            const int khalf = s >> 2, kc0 = (s & 3) * 16;
#pragma unroll
            for (int mt = 0; mt < 2; ++mt) {
                int ra = 32 * wm + 16 * mt + a_r;
                uint32_t off = khalf * 8192 + (uint32_t)swz128(ra * 128 + (kc0 + a_koff) * 2);
                uint32_t ah[4];
                ldsm4(ah[0], ah[1], ah[2], ah[3], sbase + OFF_A + off);
#pragma unroll
                for (int j = 0; j < 4; ++j) {
                    mma_f16(C[mt][j], ah, f[j].x, f[j].y);   // A*Bhi
                    mma_f16(C[mt][j], ah, f[j].z, f[j].w);   // A*Blo
                }
            }
        }

        // ---- fragment epilogue: +bias (tanh for gi>0) -> us ----
        const float* biasL = (const float*)(sm + OFF_BIAS) + gi * 128;
#pragma unroll
        for (int mt = 0; mt < 2; ++mt)
#pragma unroll
            for (int nt = 0; nt < 4; ++nt) {
                int col0 = 32 * wn + 8 * nt + 2 * (l & 3);
                float2 b2 = *(const float2*)&biasL[col0];
                float v0 = C[mt][nt][0] + b2.x, v1 = C[mt][nt][1] + b2.y;
                float v2 = C[mt][nt][2] + b2.x, v3 = C[mt][nt][3] + b2.y;
                if (gi > 0) {
                    v0 = fast_tanh(v0); v1 = fast_tanh(v1);
                    v2 = fast_tanh(v2); v3 = fast_tanh(v3);
                }
                int r = 32 * wm + 16 * mt + (l >> 2);
                *(float2*)&us[r * USP + col0]       = make_float2(v0, v1);
                *(float2*)&us[(r + 8) * USP + col0] = make_float2(v2, v3);
            }
        __syncthreads();

        const float* urow = us + erow * USP;
        if (gi == 0) {
#pragma unroll
            for (int m = 0; m < 8; ++m) {
                float4 v = *(const float4*)&urow[16 * m + 4 * q];
                hp[2 * m]     = pack2(v.x, v.y);
                hp[2 * m + 1] = pack2(v.z, v.w);
                write_A4(sm, erow, 16 * m + 4 * q, v.x, v.y, v.z, v.w);
            }
        } else {
            ull uP[16];
#pragma unroll
            for (int m = 0; m < 8; ++m) {
                float4 v = *(const float4*)&urow[16 * m + 4 * q];
                uP[2 * m]     = pack2(v.x, v.y);
                uP[2 * m + 1] = pack2(v.z, v.w);
            }

            // moments S_k = sum u^k h, T_k = sum u^k (packed pairs); T_0 known
            const ull ONE2 = 0x3F8000003F800000ull;
            ull Sa[NK], Ta[NK];
#pragma unroll
            for (int k = 0; k < NK; ++k) { Sa[k] = 0ull; Ta[k] = 0ull; }
#pragma unroll
            for (int m = 0; m < 16; ++m) {
                ull pw = uP[m];
                Sa[0] = fma2(ONE2, hp[m], Sa[0]);
#pragma unroll
                for (int k = 1; k < NK; ++k) {
                    Sa[k] = fma2(pw, hp[m], Sa[k]);
                    Ta[k] = add2(Ta[k], pw);
                    pw = mul2(pw, uP[m]);
                }
            }
            ull S2[NK], T2[NK];
#pragma unroll
            for (int k = 0; k < NK; ++k) {
                float s = plo(Sa[k]) + phi(Sa[k]);
                float tt = (k == 0) ? 32.0f : (plo(Ta[k]) + phi(Ta[k]));
                s += __shfl_xor_sync(0xffffffffu, s, 1);
                s += __shfl_xor_sync(0xffffffffu, s, 2);
                if (k == 0) {
                    tt = 128.0f;
                } else {
                    tt += __shfl_xor_sync(0xffffffffu, tt, 1);
                    tt += __shfl_xor_sync(0xffffffffu, tt, 2);
                }
                s *= cf[k];
                tt *= cf[k];
                S2[k] = pack2(s, s);
                T2[k] = pack2(tt, tt);
            }
            // Horner: y = h + N(u)/D(u); LN stats; overwrite hp with y
            float sum = 0.0f, sq = 0.0f;
#pragma unroll
            for (int m = 0; m < 16; ++m) {
                ull N = S2[NK - 1], D = T2[NK - 1];
#pragma unroll
                for (int k = NK - 2; k >= 0; --k) {
                    N = fma2(N, uP[m], S2[k]);
                    D = fma2(D, uP[m], T2[k]);
                }
                float y0 = plo(hp[m]) + __fdividef(plo(N), plo(D));
                float y1 = phi(hp[m]) + __fdividef(phi(N), phi(D));
                hp[m] = pack2(y0, y1);
                sum += y0 + y1;
                sq = fmaf(y0, y0, sq);
                sq = fmaf(y1, y1, sq);
            }
            sum += __shfl_xor_sync(0xffffffffu, sum, 1);
            sum += __shfl_xor_sync(0xffffffffu, sum, 2);
            sq  += __shfl_xor_sync(0xffffffffu, sq, 1);
            sq  += __shfl_xor_sync(0xffffffffu, sq, 2);
            float mu = sum * (1.0f / H);
            float rs = rsqrtf(sq * (1.0f / H) - mu * mu + EPS);
            const float* gam = (const float*)(sm + OFF_GAM) + (gi - 1) * 128;
            const float* bet = (const float*)(sm + OFF_BET) + (gi - 1) * 128;
#pragma unroll
            for (int m = 0; m < 8; ++m) {
                int c0 = 16 * m + 4 * q;
                float4 g4 = *(const float4*)&gam[c0];
                float4 be4 = *(const float4*)&bet[c0];
                float h0 = (plo(hp[2*m])   - mu) * rs * g4.x + be4.x;
                float h1 = (phi(hp[2*m])   - mu) * rs * g4.y + be4.y;
                float h2 = (plo(hp[2*m+1]) - mu) * rs * g4.z + be4.z;
                float h3 = (phi(hp[2*m+1]) - mu) * rs * g4.w + be4.w;
                hp[2*m]     = pack2(h0, h1);
                hp[2*m + 1] = pack2(h2, h3);
                if (gi < 3) write_A4(sm, erow, c0, h0, h1, h2, h3);
            }
        }
        __syncthreads();
    }

    // ---- classifier: logits = h @ W_c + b_c ----
    {
        const float* wc = (const float*)(sm + OFF_WC);
        float a[10];
#pragma unroll
        for (int c = 0; c < 10; ++c) a[c] = 0.0f;
#pragma unroll
        for (int m = 0; m < 16; ++m) {
#pragma unroll
            for (int pp = 0; pp < 2; ++pp) {
                int col = 16 * (m >> 1) + 4 * q + 2 * (m & 1) + pp;
                float hv = pp ? phi(hp[m]) : plo(hp[m]);
                const float4* wr = (const float4*)&wc[col * 12];
                float4 w0 = wr[0], w1 = wr[1], w2 = wr[2];
                a[0] = fmaf(hv, w0.x, a[0]);  a[1] = fmaf(hv, w0.y, a[1]);
                a[2] = fmaf(hv, w0.z, a[2]);  a[3] = fmaf(hv, w0.w, a[3]);
                a[4] = fmaf(hv, w1.x, a[4]);  a[5] = fmaf(hv, w1.y, a[5]);
                a[6] = fmaf(hv, w1.z, a[6]);  a[7] = fmaf(hv, w1.w, a[7]);
                a[8] = fmaf(hv, w2.x, a[8]);  a[9] = fmaf(hv, w2.y, a[9]);
            }
        }
#pragma unroll
        for (int c = 0; c < NC; ++c) {
            a[c] += __shfl_xor_sync(0xffffffffu, a[c], 1);
            a[c] += __shfl_xor_sync(0xffffffffu, a[c], 2);
        }
        if (q == 0) {
            const float* bc = (const float*)(sm + OFF_BC);
#pragma unroll
            for (int c = 0; c < NC; ++c)
                out[(row0 + erow) * NC + c] = a[c] + bc[c];
        }
    }
}

}  // namespace

extern "C" void kernel_launch(void* const* d_in, const int* in_sizes, int n_in,
                              void* d_out, int out_size)
{
    const float* x     = (const float*)d_in[0];
    const float* W_in  = (const float*)d_in[1];
    const float* b_in  = (const float*)d_in[2];
    const float* W_att = (const float*)d_in[3];
    const float* b_att = (const float*)d_in[4];
    const float* gamma = (const float*)d_in[5];
    const float* beta  = (const float*)d_in[6];
    const float* W_c   = (const float*)d_in[7];
    const float* b_c   = (const float*)d_in[8];
    float* out = (float*)d_out;

    convert_weights<<<64, 256>>>(W_in, W_att);

    const int B = in_sizes[0] / H;
    const int grid = B / TB;                  // 16384/64 = 256 CTAs, 2 per SM

    cudaFuncSetAttribute(fused_kernel,
                         cudaFuncAttributeMaxDynamicSharedMemorySize, SMEM_BYTES);
    fused_kernel<<<grid, NT, SMEM_BYTES>>>(x, b_in, b_att, gamma, beta, W_c, b_c, out);
}

// round 16
// speedup vs baseline: 1.4193x; 1.0672x over previous
#include <cuda_runtime.h>
#include <cuda_fp16.h>
#include <stdint.h>
#include <math.h>

namespace {
typedef unsigned long long ull;

constexpr int H = 128, TB = 64, NT = 256, NC = 10, NK = 8;
constexpr float EPS = 1e-5f;
constexpr int USP = 132;                     // us row pitch (floats)

// ---- SMEM byte offsets (from 1024-aligned base) ----
constexpr int OFF_A    = 0;                        // fp16 A tile 64x128: 2 k-halves x 8KB
constexpr int OFF_US   = 16384;                    // float[64][USP]
constexpr int OFF_WC   = OFF_US + TB * USP * 4;    // float[128][12]
constexpr int OFF_BIAS = OFF_WC + 128 * 12 * 4;    // float[4][128]
constexpr int OFF_GAM  = OFF_BIAS + 4 * 128 * 4;   // float[3][128]
constexpr int OFF_BET  = OFF_GAM + 3 * 128 * 4;
constexpr int OFF_BC   = OFF_BET + 3 * 128 * 4;    // float[16]
constexpr int SMEM_BYTES = OFF_BC + 64 + 1024;

// Weights as plain fp16 mma B fragments, TWO n-tiles per uint4:
// index = ((layer*8 + tp)*8 + kstep)*32 + lane,  tp = ntile_pair (0..7)
// payload = {b0(nt=2tp), b1(nt=2tp), b0(nt=2tp+1), b1(nt=2tp+1)}
constexpr int NFRAG2 = 4 * 8 * 8 * 32;
__device__ uint4 g_b2[NFRAG2];

__host__ __device__ __forceinline__ int swz128(int b) { return b ^ ((b >> 3) & 0x70); }

__device__ __forceinline__ uint32_t smem_u32(const void* p) {
    uint32_t a;
    asm("{ .reg .u64 t; cvta.to.shared.u64 t, %1; cvt.u32.u64 %0, t; }" : "=r"(a) : "l"(p));
    return a;
}

// ---- f32x2 packed math ----
__device__ __forceinline__ ull fma2(ull a, ull b, ull c) {
    ull d; asm("fma.rn.f32x2 %0, %1, %2, %3;" : "=l"(d) : "l"(a), "l"(b), "l"(c)); return d;
}
__device__ __forceinline__ ull add2(ull a, ull b) {
    ull d; asm("add.rn.f32x2 %0, %1, %2;" : "=l"(d) : "l"(a), "l"(b)); return d;
}
__device__ __forceinline__ ull mul2(ull a, ull b) {
    ull d; asm("mul.rn.f32x2 %0, %1, %2;" : "=l"(d) : "l"(a), "l"(b)); return d;
}
__device__ __forceinline__ ull pack2(float lo, float hi) {
    ull d; asm("mov.b64 %0, {%1, %2};" : "=l"(d) : "f"(lo), "f"(hi)); return d;
}
__device__ __forceinline__ float plo(ull v) { return __uint_as_float((unsigned)v); }
__device__ __forceinline__ float phi(ull v) { return __uint_as_float((unsigned)(v >> 32)); }

__device__ __forceinline__ void ldsm4(uint32_t& r0, uint32_t& r1, uint32_t& r2,
                                      uint32_t& r3, uint32_t addr) {
    asm volatile("ldmatrix.sync.aligned.m8n8.x4.shared.b16 {%0,%1,%2,%3}, [%4];"
                 : "=r"(r0), "=r"(r1), "=r"(r2), "=r"(r3) : "r"(addr));
}
__device__ __forceinline__ void mma_f16(float* c, const uint32_t* a,
                                        uint32_t b0, uint32_t b1) {
    asm volatile("mma.sync.aligned.m16n8k16.row.col.f32.f16.f16.f32 "
                 "{%0,%1,%2,%3}, {%4,%5,%6,%7}, {%8,%9}, {%0,%1,%2,%3};"
                 : "+f"(c[0]), "+f"(c[1]), "+f"(c[2]), "+f"(c[3])
                 : "r"(a[0]), "r"(a[1]), "r"(a[2]), "r"(a[3]), "r"(b0), "r"(b1));
}

__device__ __forceinline__ float fast_tanh(float x) {
    float a = fabsf(x);
    float e = __expf(-2.0f * a);
    float t = __fdividef(1.0f - e, 1.0f + e);
    return copysignf(t, x);
}
__device__ __forceinline__ uint32_t packh2(float a, float b) {
    __half2 p = __floats2half2_rn(a, b);
    return *reinterpret_cast<uint32_t*>(&p);
}
__device__ __forceinline__ ull packf16x4(float a, float b, float c, float d) {
    return (ull)packh2(a, b) | ((ull)packh2(c, d) << 32);
}

// One-time: W[k][n] fp32 -> plain fp16 per-lane mma B fragments, 2 n-tiles/uint4.
// m16n8k16 B fragment: lane l, reg0 holds B[2*(l%4)+{0,1}][l/4], reg1 k+8.
__global__ void convert_weights(const float* __restrict__ W_in,
                                const float* __restrict__ W_att) {
    int gidx = blockIdx.x * blockDim.x + threadIdx.x;   // 8192
    if (gidx >= NFRAG2) return;
    int lane = gidx & 31;
    int s    = (gidx >> 5) & 7;
    int tp   = (gidx >> 8) & 7;
    int layer = gidx >> 11;
    const float* W = (layer == 0) ? W_in : (W_att + (size_t)(layer - 1) * H * H);
    int n0 = 8 * (2 * tp)     + (lane >> 2);
    int n1 = 8 * (2 * tp + 1) + (lane >> 2);
    int k0 = 16 * s + 2 * (lane & 3);
    uint4 f;
    f.x = packh2(W[(k0 + 0) * H + n0], W[(k0 + 1) * H + n0]);
    f.y = packh2(W[(k0 + 8) * H + n0], W[(k0 + 9) * H + n0]);
    f.z = packh2(W[(k0 + 0) * H + n1], W[(k0 + 1) * H + n1]);
    f.w = packh2(W[(k0 + 8) * H + n1], W[(k0 + 9) * H + n1]);
    g_b2[gidx] = f;
}

// Write 4 consecutive cols (4-aligned c0) of row into the swizzled fp16 A tile.
__device__ __forceinline__ void write_A4(char* sm, int row, int c0,
                                         float v0, float v1, float v2, float v3) {
    int byz = (c0 >> 6) * 8192 + swz128(row * 128 + (c0 & 63) * 2);
    *(ull*)(sm + OFF_A + byz) = packf16x4(v0, v1, v2, v3);
}

__global__ void __launch_bounds__(NT, 2)
fused_kernel(const float* __restrict__ x,
             const float* __restrict__ b_in,
             const float* __restrict__ b_att,
             const float* __restrict__ gamma_,
             const float* __restrict__ beta_,
             const float* __restrict__ W_c,
             const float* __restrict__ b_c,
             float* __restrict__ out)
{
    extern __shared__ char smraw[];
    char* sm = (char*)(((uintptr_t)smraw + 1023) & ~(uintptr_t)1023);
    const int t = threadIdx.x, l = t & 31, w = t >> 5;
    const int wm = w & 1, wn = w >> 1;           // warp tile: rows 32wm.., cols 32wn..
    const int erow = t >> 2, q = t & 3;          // epilogue: row (0..63), chunk residue
    const long row0 = (long)blockIdx.x * TB;
    const uint32_t sbase = smem_u32(sm);

    // ldmatrix per-lane address components
    const int a_r = l & 15;
    const int a_koff = (l >> 4) * 8;

    // ---- init: x -> A tile (64 rows, fp16), params ----
#pragma unroll
    for (int it = 0; it < 8; ++it) {
        int fidx = t + NT * it;                  // 2048 float4s
        int r = fidx >> 5, c4 = fidx & 31;
        float4 xv = *(const float4*)&x[(row0 + r) * H + 4 * c4];
        int sz = (c4 >> 4) * 8192 + swz128(r * 128 + ((4 * c4) & 63) * 2);
        *(ull*)(sm + OFF_A + sz) = packf16x4(xv.x, xv.y, xv.z, xv.w);
    }
    if (t < H) {
        ((float*)(sm + OFF_BIAS))[t] = b_in[t];
#pragma unroll
        for (int i = 0; i < 3; ++i) {
            ((float*)(sm + OFF_BIAS))[(i + 1) * 128 + t] = b_att[i * H + t];
            ((float*)(sm + OFF_GAM))[i * 128 + t] = gamma_[i * H + t];
            ((float*)(sm + OFF_BET))[i * 128 + t] = beta_[i * H + t];
        }
    }
    for (int idx = t; idx < 128 * 12; idx += NT) {
        int col = idx / 12, c = idx % 12;
        ((float*)(sm + OFF_WC))[idx] = (c < NC) ? W_c[col * NC + c] : 0.0f;
    }
    if (t < NC) ((float*)(sm + OFF_BC))[t] = b_c[t];
    __syncthreads();

    // Degree-7 polynomial fit of exp on [-1,1] (Chebyshev; max abs err ~2.3e-7)
    const float cf[NK] = {
        0.9999998013203222f, 0.9999999009433100f, 0.5000063116460630f,
        0.1666679855982844f, 0.0416350112309906f, 0.0083285961068067f,
        0.0014392748705062f, 0.0002046999336094f };

    ull hp[16];          // this thread's h: chunk m -> cols 16m+4q+{0,1} and {2,3}
    float* us = (float*)(sm + OFF_US);

    for (int gi = 0; gi < 4; ++gi) {
        // ---- mainloop: C = A @ W, plain fp16 MMA, B streamed from L2 ----
        float C[2][4][4];
#pragma unroll
        for (int mt = 0; mt < 2; ++mt)
#pragma unroll
            for (int nt = 0; nt < 4; ++nt)
#pragma unroll
                for (int e2 = 0; e2 < 4; ++e2) C[mt][nt][e2] = 0.0f;

        const uint4* bf_base = g_b2 + ((gi * 8 + 2 * wn) * 8) * 32 + l;
#pragma unroll
        for (int s = 0; s < 8; ++s) {
            uint4 f01 = __ldg(bf_base + s * 32);         // n-tiles 4wn+0, 4wn+1
            uint4 f23 = __ldg(bf_base + (8 + s) * 32);   // n-tiles 4wn+2, 4wn+3

            const int khalf = s >> 2, kc0 = (s & 3) * 16;
#pragma unroll
            for (int mt = 0; mt < 2; ++mt) {
                int ra = 32 * wm + 16 * mt + a_r;
                uint32_t off = khalf * 8192 + (uint32_t)swz128(ra * 128 + (kc0 + a_koff) * 2);
                uint32_t ah[4];
                ldsm4(ah[0], ah[1], ah[2], ah[3], sbase + OFF_A + off);
                mma_f16(C[mt][0], ah, f01.x, f01.y);
                mma_f16(C[mt][1], ah, f01.z, f01.w);
                mma_f16(C[mt][2], ah, f23.x, f23.y);
                mma_f16(C[mt][3], ah, f23.z, f23.w);
            }
        }

        // ---- fragment epilogue: +bias (tanh for gi>0) -> us ----
        const float* biasL = (const float*)(sm + OFF_BIAS) + gi * 128;
#pragma unroll
        for (int mt = 0; mt < 2; ++mt)
#pragma unroll
            for (int nt = 0; nt < 4; ++nt) {
                int col0 = 32 * wn + 8 * nt + 2 * (l & 3);
                float2 b2 = *(const float2*)&biasL[col0];
                float v0 = C[mt][nt][0] + b2.x, v1 = C[mt][nt][1] + b2.y;
                float v2 = C[mt][nt][2] + b2.x, v3 = C[mt][nt][3] + b2.y;
                if (gi > 0) {
                    v0 = fast_tanh(v0); v1 = fast_tanh(v1);
                    v2 = fast_tanh(v2); v3 = fast_tanh(v3);
                }
                int r = 32 * wm + 16 * mt + (l >> 2);
                *(float2*)&us[r * USP + col0]       = make_float2(v0, v1);
                *(float2*)&us[(r + 8) * USP + col0] = make_float2(v2, v3);
            }
        __syncthreads();

        const float* urow = us + erow * USP;
        if (gi == 0) {
#pragma unroll
            for (int m = 0; m < 8; ++m) {
                float4 v = *(const float4*)&urow[16 * m + 4 * q];
                hp[2 * m]     = pack2(v.x, v.y);
                hp[2 * m + 1] = pack2(v.z, v.w);
                write_A4(sm, erow, 16 * m + 4 * q, v.x, v.y, v.z, v.w);
            }
        } else {
            ull uP[16];
#pragma unroll
            for (int m = 0; m < 8; ++m) {
                float4 v = *(const float4*)&urow[16 * m + 4 * q];
                uP[2 * m]     = pack2(v.x, v.y);
                uP[2 * m + 1] = pack2(v.z, v.w);
            }

            // moments S_k = sum u^k h, T_k = sum u^k (packed pairs); T_0 known
            const ull ONE2 = 0x3F8000003F800000ull;
            ull Sa[NK], Ta[NK];
#pragma unroll
            for (int k = 0; k < NK; ++k) { Sa[k] = 0ull; Ta[k] = 0ull; }
#pragma unroll
            for (int m = 0; m < 16; ++m) {
                ull pw = uP[m];
                Sa[0] = fma2(ONE2, hp[m], Sa[0]);
#pragma unroll
                for (int k = 1; k < NK; ++k) {
                    Sa[k] = fma2(pw, hp[m], Sa[k]);
                    Ta[k] = add2(Ta[k], pw);
                    pw = mul2(pw, uP[m]);
                }
            }
            ull S2[NK], T2[NK];
#pragma unroll
            for (int k = 0; k < NK; ++k) {
                float s = plo(Sa[k]) + phi(Sa[k]);
                float tt = (k == 0) ? 32.0f : (plo(Ta[k]) + phi(Ta[k]));
                s += __shfl_xor_sync(0xffffffffu, s, 1);
                s += __shfl_xor_sync(0xffffffffu, s, 2);
                if (k == 0) {
                    tt = 128.0f;
                } else {
                    tt += __shfl_xor_sync(0xffffffffu, tt, 1);
                    tt += __shfl_xor_sync(0xffffffffu, tt, 2);
                }
                s *= cf[k];
                tt *= cf[k];
                S2[k] = pack2(s, s);
                T2[k] = pack2(tt, tt);
            }
            // Horner: y = h + N(u)/D(u); LN stats; overwrite hp with y
            float sum = 0.0f, sq = 0.0f;
#pragma unroll
            for (int m = 0; m < 16; ++m) {
                ull N = S2[NK - 1], D = T2[NK - 1];
#pragma unroll
                for (int k = NK - 2; k >= 0; --k) {
                    N = fma2(N, uP[m], S2[k]);
                    D = fma2(D, uP[m], T2[k]);
                }
                float y0 = plo(hp[m]) + __fdividef(plo(N), plo(D));
                float y1 = phi(hp[m]) + __fdividef(phi(N), phi(D));
                hp[m] = pack2(y0, y1);
                sum += y0 + y1;
                sq = fmaf(y0, y0, sq);
                sq = fmaf(y1, y1, sq);
            }
            sum += __shfl_xor_sync(0xffffffffu, sum, 1);
            sum += __shfl_xor_sync(0xffffffffu, sum, 2);
            sq  += __shfl_xor_sync(0xffffffffu, sq, 1);
            sq  += __shfl_xor_sync(0xffffffffu, sq, 2);
            float mu = sum * (1.0f / H);
            float rs = rsqrtf(sq * (1.0f / H) - mu * mu + EPS);
            const float* gam = (const float*)(sm + OFF_GAM) + (gi - 1) * 128;
            const float* bet = (const float*)(sm + OFF_BET) + (gi - 1) * 128;
#pragma unroll
            for (int m = 0; m < 8; ++m) {
                int c0 = 16 * m + 4 * q;
                float4 g4 = *(const float4*)&gam[c0];
                float4 be4 = *(const float4*)&bet[c0];
                float h0 = (plo(hp[2*m])   - mu) * rs * g4.x + be4.x;
                float h1 = (phi(hp[2*m])   - mu) * rs * g4.y + be4.y;
                float h2 = (plo(hp[2*m+1]) - mu) * rs * g4.z + be4.z;
                float h3 = (phi(hp[2*m+1]) - mu) * rs * g4.w + be4.w;
                hp[2*m]     = pack2(h0, h1);
                hp[2*m + 1] = pack2(h2, h3);
                if (gi < 3) write_A4(sm, erow, c0, h0, h1, h2, h3);
            }
        }
        __syncthreads();
    }

    // ---- classifier: logits = h @ W_c + b_c ----
    {
        const float* wc = (const float*)(sm + OFF_WC);
        float a[10];
#pragma unroll
        for (int c = 0; c < 10; ++c) a[c] = 0.0f;
#pragma unroll
        for (int m = 0; m < 16; ++m) {
#pragma unroll
            for (int pp = 0; pp < 2; ++pp) {
                int col = 16 * (m >> 1) + 4 * q + 2 * (m & 1) + pp;
                float hv = pp ? phi(hp[m]) : plo(hp[m]);
                const float4* wr = (const float4*)&wc[col * 12];
                float4 w0 = wr[0], w1 = wr[1], w2 = wr[2];
                a[0] = fmaf(hv, w0.x, a[0]);  a[1] = fmaf(hv, w0.y, a[1]);
                a[2] = fmaf(hv, w0.z, a[2]);  a[3] = fmaf(hv, w0.w, a[3]);
                a[4] = fmaf(hv, w1.x, a[4]);  a[5] = fmaf(hv, w1.y, a[5]);
                a[6] = fmaf(hv, w1.z, a[6]);  a[7] = fmaf(hv, w1.w, a[7]);
                a[8] = fmaf(hv, w2.x, a[8]);  a[9] = fmaf(hv, w2.y, a[9]);
            }
        }
#pragma unroll
        for (int c = 0; c < NC; ++c) {
            a[c] += __shfl_xor_sync(0xffffffffu, a[c], 1);
            a[c] += __shfl_xor_sync(0xffffffffu, a[c], 2);
        }
        if (q == 0) {
            const float* bc = (const float*)(sm + OFF_BC);
#pragma unroll
            for (int c = 0; c < NC; ++c)
                out[(row0 + erow) * NC + c] = a[c] + bc[c];
        }
    }
}

}  // namespace

extern "C" void kernel_launch(void* const* d_in, const int* in_sizes, int n_in,
                              void* d_out, int out_size)
{
    const float* x     = (const float*)d_in[0];
    const float* W_in  = (const float*)d_in[1];
    const float* b_in  = (const float*)d_in[2];
    const float* W_att = (const float*)d_in[3];
    const float* b_att = (const float*)d_in[4];
    const float* gamma = (const float*)d_in[5];
    const float* beta  = (const float*)d_in[6];
    const float* W_c   = (const float*)d_in[7];
    const float* b_c   = (const float*)d_in[8];
    float* out = (float*)d_out;

    convert_weights<<<32, 256>>>(W_in, W_att);

    const int B = in_sizes[0] / H;
    const int grid = B / TB;                  // 16384/64 = 256 CTAs, 2 per SM

    cudaFuncSetAttribute(fused_kernel,
                         cudaFuncAttributeMaxDynamicSharedMemorySize, SMEM_BYTES);
    fused_kernel<<<grid, NT, SMEM_BYTES>>>(x, b_in, b_att, gamma, beta, W_c, b_c, out);
}

// round 17
// speedup vs baseline: 1.6663x; 1.1740x over previous
#include <cuda_runtime.h>
#include <cuda_fp16.h>
#include <stdint.h>
#include <math.h>

namespace {
typedef unsigned long long ull;

constexpr int H = 128, TB = 64, NT = 256, NC = 10, NK = 6;
constexpr float EPS = 1e-5f;
constexpr int USP = 132;                     // us row pitch (floats)

// ---- SMEM byte offsets (from 1024-aligned base) ----
constexpr int OFF_A    = 0;                        // fp16 A tile 64x128: 2 k-halves x 8KB
constexpr int OFF_US   = 16384;                    // float[64][USP]
constexpr int OFF_WC   = OFF_US + TB * USP * 4;    // float[128][12]
constexpr int OFF_BIAS = OFF_WC + 128 * 12 * 4;    // float[4][128]
constexpr int OFF_GAM  = OFF_BIAS + 4 * 128 * 4;   // float[3][128]
constexpr int OFF_BET  = OFF_GAM + 3 * 128 * 4;
constexpr int OFF_BC   = OFF_BET + 3 * 128 * 4;    // float[16]
constexpr int SMEM_BYTES = OFF_BC + 64 + 1024;

// Weights as plain fp16 mma B fragments, TWO n-tiles per uint4:
// index = ((layer*8 + tp)*8 + kstep)*32 + lane,  tp = ntile_pair (0..7)
// payload = {b0(nt=2tp), b1(nt=2tp), b0(nt=2tp+1), b1(nt=2tp+1)}
constexpr int NFRAG2 = 4 * 8 * 8 * 32;
__device__ uint4 g_b2[NFRAG2];

__host__ __device__ __forceinline__ int swz128(int b) { return b ^ ((b >> 3) & 0x70); }

__device__ __forceinline__ uint32_t smem_u32(const void* p) {
    uint32_t a;
    asm("{ .reg .u64 t; cvta.to.shared.u64 t, %1; cvt.u32.u64 %0, t; }" : "=r"(a) : "l"(p));
    return a;
}

// ---- f32x2 packed math ----
__device__ __forceinline__ ull fma2(ull a, ull b, ull c) {
    ull d; asm("fma.rn.f32x2 %0, %1, %2, %3;" : "=l"(d) : "l"(a), "l"(b), "l"(c)); return d;
}
__device__ __forceinline__ ull add2(ull a, ull b) {
    ull d; asm("add.rn.f32x2 %0, %1, %2;" : "=l"(d) : "l"(a), "l"(b)); return d;
}
__device__ __forceinline__ ull mul2(ull a, ull b) {
    ull d; asm("mul.rn.f32x2 %0, %1, %2;" : "=l"(d) : "l"(a), "l"(b)); return d;
}
__device__ __forceinline__ ull pack2(float lo, float hi) {
    ull d; asm("mov.b64 %0, {%1, %2};" : "=l"(d) : "f"(lo), "f"(hi)); return d;
}
__device__ __forceinline__ float plo(ull v) { return __uint_as_float((unsigned)v); }
__device__ __forceinline__ float phi(ull v) { return __uint_as_float((unsigned)(v >> 32)); }

__device__ __forceinline__ void ldsm4(uint32_t& r0, uint32_t& r1, uint32_t& r2,
                                      uint32_t& r3, uint32_t addr) {
    asm volatile("ldmatrix.sync.aligned.m8n8.x4.shared.b16 {%0,%1,%2,%3}, [%4];"
                 : "=r"(r0), "=r"(r1), "=r"(r2), "=r"(r3) : "r"(addr));
}
__device__ __forceinline__ void mma_f16(float* c, const uint32_t* a,
                                        uint32_t b0, uint32_t b1) {
    asm volatile("mma.sync.aligned.m16n8k16.row.col.f32.f16.f16.f32 "
                 "{%0,%1,%2,%3}, {%4,%5,%6,%7}, {%8,%9}, {%0,%1,%2,%3};"
                 : "+f"(c[0]), "+f"(c[1]), "+f"(c[2]), "+f"(c[3])
                 : "r"(a[0]), "r"(a[1]), "r"(a[2]), "r"(a[3]), "r"(b0), "r"(b1));
}

__device__ __forceinline__ float fast_tanh(float x) {
    float a = fabsf(x);
    float e = __expf(-2.0f * a);
    float t = __fdividef(1.0f - e, 1.0f + e);
    return copysignf(t, x);
}
__device__ __forceinline__ uint32_t packh2(float a, float b) {
    __half2 p = __floats2half2_rn(a, b);
    return *reinterpret_cast<uint32_t*>(&p);
}
__device__ __forceinline__ ull packf16x4(float a, float b, float c, float d) {
    return (ull)packh2(a, b) | ((ull)packh2(c, d) << 32);
}

// One-time: W[k][n] fp32 -> plain fp16 per-lane mma B fragments, 2 n-tiles/uint4.
// m16n8k16 B fragment: lane l, reg0 holds B[2*(l%4)+{0,1}][l/4], reg1 k+8.
__global__ void convert_weights(const float* __restrict__ W_in,
                                const float* __restrict__ W_att) {
    int gidx = blockIdx.x * blockDim.x + threadIdx.x;   // 8192
    if (gidx >= NFRAG2) return;
    int lane = gidx & 31;
    int s    = (gidx >> 5) & 7;
    int tp   = (gidx >> 8) & 7;
    int layer = gidx >> 11;
    const float* W = (layer == 0) ? W_in : (W_att + (size_t)(layer - 1) * H * H);
    int n0 = 8 * (2 * tp)     + (lane >> 2);
    int n1 = 8 * (2 * tp + 1) + (lane >> 2);
    int k0 = 16 * s + 2 * (lane & 3);
    uint4 f;
    f.x = packh2(W[(k0 + 0) * H + n0], W[(k0 + 1) * H + n0]);
    f.y = packh2(W[(k0 + 8) * H + n0], W[(k0 + 9) * H + n0]);
    f.z = packh2(W[(k0 + 0) * H + n1], W[(k0 + 1) * H + n1]);
    f.w = packh2(W[(k0 + 8) * H + n1], W[(k0 + 9) * H + n1]);
    g_b2[gidx] = f;
}

// Write 4 consecutive cols (4-aligned c0) of row into the swizzled fp16 A tile.
__device__ __forceinline__ void write_A4(char* sm, int row, int c0,
                                         float v0, float v1, float v2, float v3) {
    int byz = (c0 >> 6) * 8192 + swz128(row * 128 + (c0 & 63) * 2);
    *(ull*)(sm + OFF_A + byz) = packf16x4(v0, v1, v2, v3);
}

__global__ void __launch_bounds__(NT, 2)
fused_kernel(const float* __restrict__ x,
             const float* __restrict__ b_in,
             const float* __restrict__ b_att,
             const float* __restrict__ gamma_,
             const float* __restrict__ beta_,
             const float* __restrict__ W_c,
             const float* __restrict__ b_c,
             float* __restrict__ out)
{
    extern __shared__ char smraw[];
    char* sm = (char*)(((uintptr_t)smraw + 1023) & ~(uintptr_t)1023);
    const int t = threadIdx.x, l = t & 31, w = t >> 5;
    const int wm = w & 1, wn = w >> 1;           // warp tile: rows 32wm.., cols 32wn..
    const int erow = t >> 2, q = t & 3;          // epilogue: row (0..63), chunk residue
    const long row0 = (long)blockIdx.x * TB;
    const uint32_t sbase = smem_u32(sm);

    // ldmatrix per-lane address components
    const int a_r = l & 15;
    const int a_koff = (l >> 4) * 8;

    // ---- init: x -> A tile (64 rows, fp16), params ----
#pragma unroll
    for (int it = 0; it < 8; ++it) {
        int fidx = t + NT * it;                  // 2048 float4s
        int r = fidx >> 5, c4 = fidx & 31;
        float4 xv = *(const float4*)&x[(row0 + r) * H + 4 * c4];
        int sz = (c4 >> 4) * 8192 + swz128(r * 128 + ((4 * c4) & 63) * 2);
        *(ull*)(sm + OFF_A + sz) = packf16x4(xv.x, xv.y, xv.z, xv.w);
    }
    if (t < H) {
        ((float*)(sm + OFF_BIAS))[t] = b_in[t];
#pragma unroll
        for (int i = 0; i < 3; ++i) {
            ((float*)(sm + OFF_BIAS))[(i + 1) * 128 + t] = b_att[i * H + t];
            ((float*)(sm + OFF_GAM))[i * 128 + t] = gamma_[i * H + t];
            ((float*)(sm + OFF_BET))[i * 128 + t] = beta_[i * H + t];
        }
    }
    for (int idx = t; idx < 128 * 12; idx += NT) {
        int col = idx / 12, c = idx % 12;
        ((float*)(sm + OFF_WC))[idx] = (c < NC) ? W_c[col * NC + c] : 0.0f;
    }
    if (t < NC) ((float*)(sm + OFF_BC))[t] = b_c[t];
    __syncthreads();

    // Degree-5 truncated-Chebyshev fit of exp on [-1,1] (max abs err ~5e-5,
    // negligible vs the fp16 GEMM quantization error)
    const float cf[NK] = {
        1.0000447787f, 1.0000222900f, 0.4991967555f,
        0.1664888732f, 0.0437939235f, 0.0086868210f };

    ull hp[16];          // this thread's h: chunk m -> cols 16m+4q+{0,1} and {2,3}
    float* us = (float*)(sm + OFF_US);

    for (int gi = 0; gi < 4; ++gi) {
        // ---- mainloop: C = A @ W, plain fp16 MMA, B streamed from L2 ----
        float C[2][4][4];
#pragma unroll
        for (int mt = 0; mt < 2; ++mt)
#pragma unroll
            for (int nt = 0; nt < 4; ++nt)
#pragma unroll
                for (int e2 = 0; e2 < 4; ++e2) C[mt][nt][e2] = 0.0f;

        const uint4* bf_base = g_b2 + ((gi * 8 + 2 * wn) * 8) * 32 + l;
#pragma unroll
        for (int s = 0; s < 8; ++s) {
            uint4 f01 = __ldg(bf_base + s * 32);         // n-tiles 4wn+0, 4wn+1
            uint4 f23 = __ldg(bf_base + (8 + s) * 32);   // n-tiles 4wn+2, 4wn+3

            const int khalf = s >> 2, kc0 = (s & 3) * 16;
#pragma unroll
            for (int mt = 0; mt < 2; ++mt) {
                int ra = 32 * wm + 16 * mt + a_r;
                uint32_t off = khalf * 8192 + (uint32_t)swz128(ra * 128 + (kc0 + a_koff) * 2);
                uint32_t ah[4];
                ldsm4(ah[0], ah[1], ah[2], ah[3], sbase + OFF_A + off);
                mma_f16(C[mt][0], ah, f01.x, f01.y);
                mma_f16(C[mt][1], ah, f01.z, f01.w);
                mma_f16(C[mt][2], ah, f23.x, f23.y);
                mma_f16(C[mt][3], ah, f23.z, f23.w);
            }
        }

        // ---- fragment epilogue: +bias (tanh for gi>0) -> us ----
        const float* biasL = (const float*)(sm + OFF_BIAS) + gi * 128;
#pragma unroll
        for (int mt = 0; mt < 2; ++mt)
#pragma unroll
            for (int nt = 0; nt < 4; ++nt) {
                int col0 = 32 * wn + 8 * nt + 2 * (l & 3);
                float2 b2 = *(const float2*)&biasL[col0];
                float v0 = C[mt][nt][0] + b2.x, v1 = C[mt][nt][1] + b2.y;
                float v2 = C[mt][nt][2] + b2.x, v3 = C[mt][nt][3] + b2.y;
                if (gi > 0) {
                    v0 = fast_tanh(v0); v1 = fast_tanh(v1);
                    v2 = fast_tanh(v2); v3 = fast_tanh(v3);
                }
                int r = 32 * wm + 16 * mt + (l >> 2);
                *(float2*)&us[r * USP + col0]       = make_float2(v0, v1);
                *(float2*)&us[(r + 8) * USP + col0] = make_float2(v2, v3);
            }
        __syncthreads();

        const float* urow = us + erow * USP;
        if (gi == 0) {
#pragma unroll
            for (int m = 0; m < 8; ++m) {
                float4 v = *(const float4*)&urow[16 * m + 4 * q];
                hp[2 * m]     = pack2(v.x, v.y);
                hp[2 * m + 1] = pack2(v.z, v.w);
                write_A4(sm, erow, 16 * m + 4 * q, v.x, v.y, v.z, v.w);
            }
        } else {
            ull uP[16];
#pragma unroll
            for (int m = 0; m < 8; ++m) {
                float4 v = *(const float4*)&urow[16 * m + 4 * q];
                uP[2 * m]     = pack2(v.x, v.y);
                uP[2 * m + 1] = pack2(v.z, v.w);
            }

            // moments S_k = sum u^k h, T_k = sum u^k (packed pairs); T_0 known
            const ull ONE2 = 0x3F8000003F800000ull;
            ull Sa[NK], Ta[NK];
#pragma unroll
            for (int k = 0; k < NK; ++k) { Sa[k] = 0ull; Ta[k] = 0ull; }
#pragma unroll
            for (int m = 0; m < 16; ++m) {
                ull pw = uP[m];
                Sa[0] = fma2(ONE2, hp[m], Sa[0]);
#pragma unroll
                for (int k = 1; k < NK; ++k) {
                    Sa[k] = fma2(pw, hp[m], Sa[k]);
                    Ta[k] = add2(Ta[k], pw);
                    pw = mul2(pw, uP[m]);
                }
            }
            ull S2[NK], T2[NK];
#pragma unroll
            for (int k = 0; k < NK; ++k) {
                float s = plo(Sa[k]) + phi(Sa[k]);
                float tt = (k == 0) ? 32.0f : (plo(Ta[k]) + phi(Ta[k]));
                s += __shfl_xor_sync(0xffffffffu, s, 1);
                s += __shfl_xor_sync(0xffffffffu, s, 2);
                if (k == 0) {
                    tt = 128.0f;
                } else {
                    tt += __shfl_xor_sync(0xffffffffu, tt, 1);
                    tt += __shfl_xor_sync(0xffffffffu, tt, 2);
                }
                s *= cf[k];
                tt *= cf[k];
                S2[k] = pack2(s, s);
                T2[k] = pack2(tt, tt);
            }
            // Horner: y = h + N(u)/D(u); LN stats; overwrite hp with y
            float sum = 0.0f, sq = 0.0f;
#pragma unroll
            for (int m = 0; m < 16; ++m) {
                ull N = S2[NK - 1], D = T2[NK - 1];
#pragma unroll
                for (int k = NK - 2; k >= 0; --k) {
                    N = fma2(N, uP[m], S2[k]);
                    D = fma2(D, uP[m], T2[k]);
                }
                float y0 = plo(hp[m]) + __fdividef(plo(N), plo(D));
                float y1 = phi(hp[m]) + __fdividef(phi(N), phi(D));
                hp[m] = pack2(y0, y1);
                sum += y0 + y1;
                sq = fmaf(y0, y0, sq);
                sq = fmaf(y1, y1, sq);
            }
            sum += __shfl_xor_sync(0xffffffffu, sum, 1);
            sum += __shfl_xor_sync(0xffffffffu, sum, 2);
            sq  += __shfl_xor_sync(0xffffffffu, sq, 1);
            sq  += __shfl_xor_sync(0xffffffffu, sq, 2);
            float mu = sum * (1.0f / H);
            float rs = rsqrtf(sq * (1.0f / H) - mu * mu + EPS);
            const float* gam = (const float*)(sm + OFF_GAM) + (gi - 1) * 128;
            const float* bet = (const float*)(sm + OFF_BET) + (gi - 1) * 128;
#pragma unroll
            for (int m = 0; m < 8; ++m) {
                int c0 = 16 * m + 4 * q;
                float4 g4 = *(const float4*)&gam[c0];
                float4 be4 = *(const float4*)&bet[c0];
                float h0 = (plo(hp[2*m])   - mu) * rs * g4.x + be4.x;
                float h1 = (phi(hp[2*m])   - mu) * rs * g4.y + be4.y;
                float h2 = (plo(hp[2*m+1]) - mu) * rs * g4.z + be4.z;
                float h3 = (phi(hp[2*m+1]) - mu) * rs * g4.w + be4.w;
                hp[2*m]     = pack2(h0, h1);
                hp[2*m + 1] = pack2(h2, h3);
                if (gi < 3) write_A4(sm, erow, c0, h0, h1, h2, h3);
            }
        }
        __syncthreads();
    }

    // ---- classifier: logits = h @ W_c + b_c ----
    {
        const float* wc = (const float*)(sm + OFF_WC);
        float a[10];
#pragma unroll
        for (int c = 0; c < 10; ++c) a[c] = 0.0f;
#pragma unroll
        for (int m = 0; m < 16; ++m) {
#pragma unroll
            for (int pp = 0; pp < 2; ++pp) {
                int col = 16 * (m >> 1) + 4 * q + 2 * (m & 1) + pp;
                float hv = pp ? phi(hp[m]) : plo(hp[m]);
                const float4* wr = (const float4*)&wc[col * 12];
                float4 w0 = wr[0], w1 = wr[1], w2 = wr[2];
                a[0] = fmaf(hv, w0.x, a[0]);  a[1] = fmaf(hv, w0.y, a[1]);
                a[2] = fmaf(hv, w0.z, a[2]);  a[3] = fmaf(hv, w0.w, a[3]);
                a[4] = fmaf(hv, w1.x, a[4]);  a[5] = fmaf(hv, w1.y, a[5]);
                a[6] = fmaf(hv, w1.z, a[6]);  a[7] = fmaf(hv, w1.w, a[7]);
                a[8] = fmaf(hv, w2.x, a[8]);  a[9] = fmaf(hv, w2.y, a[9]);
            }
        }
#pragma unroll
        for (int c = 0; c < NC; ++c) {
            a[c] += __shfl_xor_sync(0xffffffffu, a[c], 1);
            a[c] += __shfl_xor_sync(0xffffffffu, a[c], 2);
        }
        if (q == 0) {
            const float* bc = (const float*)(sm + OFF_BC);
#pragma unroll
            for (int c = 0; c < NC; ++c)
                out[(row0 + erow) * NC + c] = a[c] + bc[c];
        }
    }
}

}  // namespace

extern "C" void kernel_launch(void* const* d_in, const int* in_sizes, int n_in,
                              void* d_out, int out_size)
{
    const float* x     = (const float*)d_in[0];
    const float* W_in  = (const float*)d_in[1];
    const float* b_in  = (const float*)d_in[2];
    const float* W_att = (const float*)d_in[3];
    const float* b_att = (const float*)d_in[4];
    const float* gamma = (const float*)d_in[5];
    const float* beta  = (const float*)d_in[6];
    const float* W_c   = (const float*)d_in[7];
    const float* b_c   = (const float*)d_in[8];
    float* out = (float*)d_out;

    convert_weights<<<32, 256>>>(W_in, W_att);

    const int B = in_sizes[0] / H;
    const int grid = B / TB;                  // 16384/64 = 256 CTAs, 2 per SM

    cudaFuncSetAttribute(fused_kernel,
                         cudaFuncAttributeMaxDynamicSharedMemorySize, SMEM_BYTES);
    fused_kernel<<<grid, NT, SMEM_BYTES>>>(x, b_in, b_att, gamma, beta, W_c, b_c, out);
}